// round 13
// baseline (speedup 1.0000x reference)
#include <cuda_runtime.h>
#include <math.h>

// ---------------- problem constants ----------------
#define BB       2
#define SEQ      2048
#define DMODEL   1024
#define DCONV    4
#define HEADDIM  64
#define CHUNKL   256
#define DINNER   2048
#define NHEADS   32
#define CONVDIM  2304
#define DINPROJ  4384
#define DSTATE   128
#define DFF      4096
#define NC       8
#define NROWS    (BB*SEQ)   // 4096

// ---------------- scratch ----------------
__device__ float g_zx[(size_t)NROWS*DINPROJ];
__device__ float g_xbc[(size_t)NROWS*CONVDIM];
__device__ float g_xdt[(size_t)NROWS*DINNER];
__device__ float g_dt[(size_t)NROWS*NHEADS];
__device__ float g_draw[(size_t)NROWS*NHEADS];
__device__ float g_acum[(size_t)BB*NHEADS*SEQ];
__device__ float g_G[(size_t)BB*NC*CHUNKL*CHUNKL];
__device__ float g_states[(size_t)BB*NC*NHEADS*HEADDIM*DSTATE];
__device__ float g_prev  [(size_t)BB*NC*NHEADS*HEADDIM*DSTATE];
__device__ float g_y[(size_t)NROWS*DINNER];
__device__ float g_hidden[(size_t)NROWS*DMODEL];
__device__ float g_h[(size_t)NROWS*DMODEL];
__device__ float g_ff2[(size_t)NROWS*DMODEL];
// bf16 hi/lo packed operands (u32 = 2 bf16, k-pairs)
__device__ unsigned g_xhi[(size_t)NROWS*DMODEL/2],  g_xlo[(size_t)NROWS*DMODEL/2];
__device__ unsigned g_WinT_hi[(size_t)DINPROJ*DMODEL/2], g_WinT_lo[(size_t)DINPROJ*DMODEL/2];
__device__ unsigned g_WoutT_hi[(size_t)DMODEL*DINNER/2], g_WoutT_lo[(size_t)DMODEL*DINNER/2];
__device__ unsigned g_f1T_hi[(size_t)DFF*DMODEL/2],  g_f1T_lo[(size_t)DFF*DMODEL/2];
__device__ unsigned g_f2T_hi[(size_t)DMODEL*DFF/2],  g_f2T_lo[(size_t)DMODEL*DFF/2];
__device__ unsigned g_yhi[(size_t)NROWS*DINNER/2],   g_ylo[(size_t)NROWS*DINNER/2];
__device__ unsigned g_hhi[(size_t)NROWS*DMODEL/2],   g_hlo[(size_t)NROWS*DMODEL/2];
__device__ unsigned g_ffhi[(size_t)NROWS*DFF/2],     g_fflo[(size_t)NROWS*DFF/2];

// ---------------- helpers ----------------
__device__ __forceinline__ float softplusf(float x) {
    return (x > 20.f) ? x : log1pf(expf(x));
}
__device__ __forceinline__ float siluf(float x) {
    return x / (1.f + expf(-x));
}
__device__ __forceinline__ float tf32r(float x) {
    unsigned r;
    asm("cvt.rna.tf32.f32 %0, %1;" : "=r"(r) : "f"(x));
    return __uint_as_float(r);
}
__device__ __forceinline__ unsigned smem_u32(const void* p) {
    unsigned a;
    asm("{ .reg .u64 t; cvta.to.shared.u64 t, %1; cvt.u32.u64 %0, t; }" : "=r"(a) : "l"(p));
    return a;
}
__device__ __forceinline__ void mma_tf32(float* c, const unsigned* a, const unsigned* b) {
    asm volatile("mma.sync.aligned.m16n8k8.row.col.f32.tf32.tf32.f32 "
                 "{%0,%1,%2,%3}, {%4,%5,%6,%7}, {%8,%9}, {%0,%1,%2,%3};"
                 : "+f"(c[0]), "+f"(c[1]), "+f"(c[2]), "+f"(c[3])
                 : "r"(a[0]), "r"(a[1]), "r"(a[2]), "r"(a[3]),
                   "r"(b[0]), "r"(b[1]));
}
__device__ __forceinline__ void mma_bf16(float* c, const unsigned* a, const unsigned* b) {
    asm volatile("mma.sync.aligned.m16n8k16.row.col.f32.bf16.bf16.f32 "
                 "{%0,%1,%2,%3}, {%4,%5,%6,%7}, {%8,%9}, {%0,%1,%2,%3};"
                 : "+f"(c[0]), "+f"(c[1]), "+f"(c[2]), "+f"(c[3])
                 : "r"(a[0]), "r"(a[1]), "r"(a[2]), "r"(a[3]),
                   "r"(b[0]), "r"(b[1]));
}
__device__ __forceinline__ void ldm4(unsigned* r, unsigned addr) {
    asm volatile("ldmatrix.sync.aligned.m8n8.x4.shared.b16 {%0,%1,%2,%3}, [%4];"
                 : "=r"(r[0]), "=r"(r[1]), "=r"(r[2]), "=r"(r[3]) : "r"(addr));
}
// pack (f0 -> low bf16, f1 -> high bf16); lo = bf16 residual
__device__ __forceinline__ void split2(float f0, float f1, unsigned& hi, unsigned& lo) {
    unsigned h;
    asm("cvt.rn.bf16x2.f32 %0, %1, %2;" : "=r"(h) : "f"(f1), "f"(f0));
    float h0 = __uint_as_float(h << 16);
    float h1 = __uint_as_float(h & 0xffff0000u);
    unsigned l;
    asm("cvt.rn.bf16x2.f32 %0, %1, %2;" : "=r"(l) : "f"(f1 - h1), "f"(f0 - h0));
    hi = h; lo = l;
}

// ---------------- conversion kernels ----------------
__global__ void convA_kernel(const float* __restrict__ src, unsigned* __restrict__ hi,
                             unsigned* __restrict__ lo, int n2)
{
    int i = blockIdx.x * blockDim.x + threadIdx.x;
    if (i >= n2) return;
    float2 v = ((const float2*)src)[i];
    unsigned h, l;
    split2(v.x, v.y, h, l);
    hi[i] = h; lo[i] = l;
}
__global__ void convBT_kernel(const float* __restrict__ src, unsigned* __restrict__ hi,
                              unsigned* __restrict__ lo, int K, int N)
{
    __shared__ float ts[32][33];
    int n0 = blockIdx.x * 32, k0 = blockIdx.y * 32;
    int t = threadIdx.x;
    int r = t >> 3, c4 = (t & 7) * 4;
    float4 v = *(const float4*)(src + (size_t)(k0 + r) * N + n0 + c4);
    ts[r][c4 + 0] = v.x; ts[r][c4 + 1] = v.y; ts[r][c4 + 2] = v.z; ts[r][c4 + 3] = v.w;
    __syncthreads();
#pragma unroll
    for (int u = 0; u < 2; u++) {
        int idx = t * 2 + u;
        int n = idx >> 4, kp = idx & 15;
        unsigned h, l;
        split2(ts[2 * kp][n], ts[2 * kp + 1][n], h, l);
        size_t o = (size_t)(n0 + n) * (K / 2) + (k0 >> 1) + kp;
        hi[o] = h; lo[o] = l;
    }
}

// ---------------- bf16 hi/lo split GEMM with ldmatrix fragment loads --------
// A [M][K2] u32, B [N][K2] u32 (transposed). K2 = K/2.
// CTA 128x128, warp 32x64, 4-stage cp.async, 3 passes (hh, lh, hl).
#define GBS     4
#define RSTR    12
#define AB_STF  (128*RSTR)
#define STG_U   (4*AB_STF)
#define GB_SMEM (GBS*STG_U*4)             // 98304 bytes

#define GB_ISSUE(stg, kt) do {                                                       \
    unsigned sb = smb + (unsigned)(stg) * (STG_U * 4);                               \
    int m_ = tid >> 1, hf_ = (tid & 1) * 4;                                          \
    unsigned ko = (unsigned)(kt) * 8 + hf_;                                          \
    const unsigned* a1 = Ahi + (size_t)(row0 + m_) * K2 + ko;                        \
    const unsigned* a2 = Alo + (size_t)(row0 + m_) * K2 + ko;                        \
    unsigned d_ = (unsigned)(m_ * RSTR + hf_) * 4;                                   \
    asm volatile("cp.async.cg.shared.global [%0], [%1], 16;" :: "r"(sb + d_), "l"(a1)); \
    asm volatile("cp.async.cg.shared.global [%0], [%1], 16;"                         \
                 :: "r"(sb + AB_STF * 4 + d_), "l"(a2));                             \
    int gn_ = col0 + m_;                                                             \
    const unsigned* b1 = (gn_ < N) ? (Bhi + (size_t)gn_ * K2 + ko) : Bhi;            \
    const unsigned* b2 = (gn_ < N) ? (Blo + (size_t)gn_ * K2 + ko) : Blo;            \
    int by_ = (gn_ < N) ? 16 : 0;                                                    \
    asm volatile("cp.async.cg.shared.global [%0], [%1], 16, %2;"                     \
                 :: "r"(sb + 2 * AB_STF * 4 + d_), "l"(b1), "r"(by_));               \
    asm volatile("cp.async.cg.shared.global [%0], [%1], 16, %2;"                     \
                 :: "r"(sb + 3 * AB_STF * 4 + d_), "l"(b2), "r"(by_));               \
    asm volatile("cp.async.commit_group;" ::: "memory");                             \
} while (0)

__global__ __launch_bounds__(256)
void gemm_bf(const unsigned* __restrict__ Ahi, const unsigned* __restrict__ Alo,
             const unsigned* __restrict__ Bhi, const unsigned* __restrict__ Blo,
             const float* __restrict__ bias, float* __restrict__ C,
             unsigned* __restrict__ Chi, unsigned* __restrict__ Clo,
             int M, int N, int K2, int act)
{
    extern __shared__ unsigned smu[];
    unsigned smb = smem_u32(smu);
    int tid = threadIdx.x;
    int lane = tid & 31, wid = tid >> 5;
    int wm = (wid >> 1) * 32;
    int wn = (wid & 1) * 64;
    int g = lane >> 2, tig = lane & 3;
    int row0 = blockIdx.y * 128, col0 = blockIdx.x * 128;

    // ldmatrix per-lane byte offsets (within one operand array of a stage)
    // A x4 for m-tile mt: matrices (m0-7,klo),(m8-15,klo),(m0-7,khi),(m8-15,khi)
    unsigned a_off[2];
#pragma unroll
    for (int mt = 0; mt < 2; mt++) {
        int rowm = wm + mt * 16 + (lane & 7) + ((lane >> 3) & 1) * 8;
        int kof = (lane >> 4) * 4;
        a_off[mt] = (unsigned)(rowm * RSTR + kof) * 4;
    }
    // B x4 for n-pair j: matrices (t2j,klo),(t2j,khi),(t2j+1,klo),(t2j+1,khi)
    unsigned b_off[4];
#pragma unroll
    for (int j = 0; j < 4; j++) {
        int rown = wn + (2 * j + (lane >> 4)) * 8 + (lane & 7);
        int kof = ((lane >> 3) & 1) * 4;
        b_off[j] = (unsigned)(rown * RSTR + kof) * 4;
    }

    float acc[2][8][4];
#pragma unroll
    for (int i = 0; i < 2; i++)
#pragma unroll
        for (int j = 0; j < 8; j++)
#pragma unroll
            for (int v = 0; v < 4; v++) acc[i][j][v] = 0.f;

    int nt = K2 / 8;
    GB_ISSUE(0, 0);
    GB_ISSUE(1, 1);
    GB_ISSUE(2, 2);

    for (int t = 0; t < nt; t++) {
        if (t + 3 <= nt)      asm volatile("cp.async.wait_group 2;" ::: "memory");
        else if (t + 2 == nt) asm volatile("cp.async.wait_group 1;" ::: "memory");
        else                  asm volatile("cp.async.wait_group 0;" ::: "memory");
        __syncthreads();
        if (t + 3 < nt) { GB_ISSUE((t + 3) & 3, t + 3); }

        unsigned base = smb + (unsigned)(t & 3) * (STG_U * 4);
        unsigned bAh = base;
        unsigned bAl = base + AB_STF * 4;
        unsigned bBh = base + 2 * AB_STF * 4;
        unsigned bBl = base + 3 * AB_STF * 4;

        unsigned ah[2][4], bh[4][4];
#pragma unroll
        for (int mt = 0; mt < 2; mt++) ldm4(ah[mt], bAh + a_off[mt]);
#pragma unroll
        for (int j = 0; j < 4; j++) ldm4(bh[j], bBh + b_off[j]);
        // pass hh
#pragma unroll
        for (int mt = 0; mt < 2; mt++)
#pragma unroll
            for (int j = 0; j < 4; j++) {
                mma_bf16(acc[mt][2 * j],     ah[mt], &bh[j][0]);
                mma_bf16(acc[mt][2 * j + 1], ah[mt], &bh[j][2]);
            }
        // pass lh (A-lo x B-hi)
        {
            unsigned al[2][4];
#pragma unroll
            for (int mt = 0; mt < 2; mt++) ldm4(al[mt], bAl + a_off[mt]);
#pragma unroll
            for (int mt = 0; mt < 2; mt++)
#pragma unroll
                for (int j = 0; j < 4; j++) {
                    mma_bf16(acc[mt][2 * j],     al[mt], &bh[j][0]);
                    mma_bf16(acc[mt][2 * j + 1], al[mt], &bh[j][2]);
                }
        }
        // pass hl (A-hi x B-lo)
        {
            unsigned bl[4][4];
#pragma unroll
            for (int j = 0; j < 4; j++) ldm4(bl[j], bBl + b_off[j]);
#pragma unroll
            for (int mt = 0; mt < 2; mt++)
#pragma unroll
                for (int j = 0; j < 4; j++) {
                    mma_bf16(acc[mt][2 * j],     ah[mt], &bl[j][0]);
                    mma_bf16(acc[mt][2 * j + 1], ah[mt], &bl[j][2]);
                }
        }
    }

    // epilogue
#pragma unroll
    for (int mt = 0; mt < 2; mt++) {
        int r = row0 + wm + mt * 16 + g;
#pragma unroll
        for (int nt2 = 0; nt2 < 8; nt2++) {
            int col = col0 + wn + nt2 * 8 + 2 * tig;
            if (col < N) {
                float b0 = bias[col], b1 = bias[col + 1];
                float v0 = acc[mt][nt2][0] + b0;
                float v1 = acc[mt][nt2][1] + b1;
                float v2 = acc[mt][nt2][2] + b0;
                float v3 = acc[mt][nt2][3] + b1;
                if (act == 1) {
                    float tt;
                    tt = fminf(fmaxf(v0 + 3.f, 0.f), 6.f); v0 = v0 * tt * (1.f / 6.f);
                    tt = fminf(fmaxf(v1 + 3.f, 0.f), 6.f); v1 = v1 * tt * (1.f / 6.f);
                    tt = fminf(fmaxf(v2 + 3.f, 0.f), 6.f); v2 = v2 * tt * (1.f / 6.f);
                    tt = fminf(fmaxf(v3 + 3.f, 0.f), 6.f); v3 = v3 * tt * (1.f / 6.f);
                    unsigned h0, l0, h1, l1;
                    split2(v0, v1, h0, l0);
                    split2(v2, v3, h1, l1);
                    size_t o0 = (size_t)r * (N / 2) + (col >> 1);
                    size_t o1 = (size_t)(r + 8) * (N / 2) + (col >> 1);
                    Chi[o0] = h0; Clo[o0] = l0;
                    Chi[o1] = h1; Clo[o1] = l1;
                } else {
                    C[(size_t)r * N + col] = v0;
                    C[(size_t)r * N + col + 1] = v1;
                    C[(size_t)(r + 8) * N + col] = v2;
                    C[(size_t)(r + 8) * N + col + 1] = v3;
                }
            }
        }
    }
}

// ---------------- exact fp32 dt_raw ----------------
__global__ void dtraw_kernel(const float* __restrict__ x, const float* __restrict__ W_in,
                             const float* __restrict__ b_in)
{
    int row0 = blockIdx.x * 8;
    int tid = threadIdx.x;
    int r = tid >> 5, h = tid & 31;
    __shared__ float xs[8][DMODEL];
    for (int i = tid; i < 8 * DMODEL; i += 256)
        xs[i >> 10][i & 1023] = x[(size_t)(row0 + (i >> 10)) * DMODEL + (i & 1023)];
    __syncthreads();
    const float* wc = W_in + (DINPROJ - NHEADS) + h;
    float a0 = 0.f, a1 = 0.f, a2 = 0.f, a3 = 0.f;
#pragma unroll 2
    for (int k = 0; k < DMODEL; k += 4) {
        a0 = fmaf(xs[r][k + 0], wc[(size_t)(k + 0) * DINPROJ], a0);
        a1 = fmaf(xs[r][k + 1], wc[(size_t)(k + 1) * DINPROJ], a1);
        a2 = fmaf(xs[r][k + 2], wc[(size_t)(k + 2) * DINPROJ], a2);
        a3 = fmaf(xs[r][k + 3], wc[(size_t)(k + 3) * DINPROJ], a3);
    }
    g_draw[(size_t)(row0 + r) * NHEADS + h] =
        b_in[DINPROJ - NHEADS + h] + ((a0 + a1) + (a2 + a3));
}

// ---------------- conv + silu + fused xdt ----------------
__global__ void conv_kernel(const float* __restrict__ conv_w, const float* __restrict__ conv_b)
{
    int idx = blockIdx.x * blockDim.x + threadIdx.x;
    if (idx >= (NROWS / 4) * CONVDIM) return;
    int ch = idx % CONVDIM;
    int rg = idx / CONVDIM;
    int row0 = rg * 4;
    int l0 = row0 % SEQ;
    float w0 = conv_w[ch * DCONV + 0], w1 = conv_w[ch * DCONV + 1];
    float w2 = conv_w[ch * DCONV + 2], w3 = conv_w[ch * DCONV + 3];
    float bv = conv_b[ch];
    float v[7];
#pragma unroll
    for (int j = 0; j < 7; j++) {
        int l = l0 + j - 3;
        v[j] = (l >= 0) ? g_zx[(size_t)(row0 + j - 3) * DINPROJ + DINNER + ch] : 0.f;
    }
#pragma unroll
    for (int i = 0; i < 4; i++) {
        float a = bv;
        a = fmaf(v[i], w0, a);
        a = fmaf(v[i + 1], w1, a);
        a = fmaf(v[i + 2], w2, a);
        a = fmaf(v[i + 3], w3, a);
        float o = siluf(a);
        size_t row = row0 + i;
        g_xbc[row * CONVDIM + ch] = o;
        if (ch < DINNER)
            g_xdt[row * DINNER + ch] = o * g_dt[row * NHEADS + (ch >> 6)];
    }
}

// ---------------- dt / dA + per-chunk inclusive cumsum ----------------
__global__ void dtscan_kernel(const float* __restrict__ tdiff,
                              const float* __restrict__ A_log,
                              const float* __restrict__ dt_bias,
                              const float* __restrict__ time_decay)
{
    int blk = blockIdx.x;
    int c = blk % NC;
    int h = (blk / NC) % NHEADS;
    int b = blk / (NC * NHEADS);
    int l = threadIdx.x;
    __shared__ float s[CHUNKL];
    int row = b * SEQ + c * CHUNKL + l;
    float draw = g_draw[(size_t)row * NHEADS + h];
    float dt = softplusf(draw + dt_bias[h]);
    float Ah = -expf(A_log[h]);
    float spd = softplusf(time_decay[h]);
    float dA = dt * Ah - spd * tdiff[row];
    g_dt[(size_t)row * NHEADS + h] = dt;
    s[l] = dA;
    __syncthreads();
    for (int off = 1; off < CHUNKL; off <<= 1) {
        float v = (l >= off) ? s[l - off] : 0.f;
        __syncthreads();
        s[l] += v;
        __syncthreads();
    }
    g_acum[((size_t)(b * NHEADS + h)) * SEQ + c * CHUNKL + l] = s[l];
}

// ---------------- G = C @ B^T per (b,chunk)  [tf32 mma] ----------------
__global__ __launch_bounds__(256)
void cbgemm_kernel()
{
    int bc = blockIdx.z;
    int l0 = blockIdx.y * 64, s0 = blockIdx.x * 64;
    __shared__ float As[16][72];
    __shared__ float Bs2[16][72];
    int tid = threadIdx.x;
    int lane = tid & 31, wid = tid >> 5;
    int wm = (wid & 3) * 16;
    int wn = (wid >> 2) * 32;
    int g = lane >> 2, tig = lane & 3;

    float acc[4][4];
#pragma unroll
    for (int j = 0; j < 4; j++)
#pragma unroll
        for (int v = 0; v < 4; v++) acc[j][v] = 0.f;

    const float* base = g_xbc + (size_t)bc * CHUNKL * CONVDIM;
    int r = tid >> 2, c4 = (tid & 3) << 2;
    for (int n0 = 0; n0 < DSTATE; n0 += 16) {
        float4 vc = *(const float4*)(base + (size_t)(l0 + r) * CONVDIM + DINNER + DSTATE + n0 + c4);
        As[c4 + 0][r] = tf32r(vc.x); As[c4 + 1][r] = tf32r(vc.y);
        As[c4 + 2][r] = tf32r(vc.z); As[c4 + 3][r] = tf32r(vc.w);
        float4 vb = *(const float4*)(base + (size_t)(s0 + r) * CONVDIM + DINNER + n0 + c4);
        Bs2[c4 + 0][r] = tf32r(vb.x); Bs2[c4 + 1][r] = tf32r(vb.y);
        Bs2[c4 + 2][r] = tf32r(vb.z); Bs2[c4 + 3][r] = tf32r(vb.w);
        __syncthreads();
#pragma unroll
        for (int ks = 0; ks < 2; ks++) {
            int kb = ks * 8;
            unsigned af[4], bf[4][2];
            af[0] = __float_as_uint(As[kb + tig][wm + g]);
            af[1] = __float_as_uint(As[kb + tig][wm + g + 8]);
            af[2] = __float_as_uint(As[kb + tig + 4][wm + g]);
            af[3] = __float_as_uint(As[kb + tig + 4][wm + g + 8]);
#pragma unroll
            for (int nt = 0; nt < 4; nt++) {
                int n = wn + nt * 8;
                bf[nt][0] = __float_as_uint(Bs2[kb + tig][n + g]);
                bf[nt][1] = __float_as_uint(Bs2[kb + tig + 4][n + g]);
            }
#pragma unroll
            for (int nt = 0; nt < 4; nt++)
                mma_tf32(acc[nt], af, bf[nt]);
        }
        __syncthreads();
    }
    float* Gp = g_G + (size_t)bc * CHUNKL * CHUNKL;
    int rr = l0 + wm + g;
#pragma unroll
    for (int nt = 0; nt < 4; nt++) {
        int col = s0 + wn + nt * 8 + 2 * tig;
        Gp[(size_t)rr * CHUNKL + col]     = acc[nt][0];
        Gp[(size_t)rr * CHUNKL + col + 1] = acc[nt][1];
        Gp[(size_t)(rr + 8) * CHUNKL + col]     = acc[nt][2];
        Gp[(size_t)(rr + 8) * CHUNKL + col + 1] = acc[nt][3];
    }
}

// ---------------- chunk states  [tf32 mma, __expf] ----------------
__global__ __launch_bounds__(256)
void states_kernel()
{
    int bch = blockIdx.x;
    int h = bch % NHEADS;
    int bc = bch / NHEADS;
    int b = bc / NC, c = bc % NC;
    int tid = threadIdx.x;
    int lane = tid & 31, wid = tid >> 5;
    int wm = (wid >> 1) * 16;
    int wn = (wid & 1) * 64;
    int g = lane >> 2, tig = lane & 3;

    __shared__ float w[CHUNKL];
    __shared__ float As[16][72];
    __shared__ float Bs[16][136];
    const float* ac = g_acum + ((size_t)(b * NHEADS + h)) * SEQ + c * CHUNKL;
    w[tid] = __expf(ac[CHUNKL - 1] - ac[tid]);
    __syncthreads();

    float acc[8][4];
#pragma unroll
    for (int j = 0; j < 8; j++)
#pragma unroll
        for (int v = 0; v < 4; v++) acc[j][v] = 0.f;

    for (int l0 = 0; l0 < CHUNKL; l0 += 16) {
        {
            int lr = tid >> 4, pc = (tid & 15) << 2;
            float4 v = *(const float4*)(g_xdt + ((size_t)(bc * CHUNKL + l0 + lr)) * DINNER + h * HEADDIM + pc);
            float ww = w[l0 + lr];
            As[lr][pc + 0] = tf32r(v.x * ww); As[lr][pc + 1] = tf32r(v.y * ww);
            As[lr][pc + 2] = tf32r(v.z * ww); As[lr][pc + 3] = tf32r(v.w * ww);
        }
#pragma unroll
        for (int u = 0; u < 2; u++) {
            int id = tid * 2 + u;
            int lr2 = id >> 5, nc4 = (id & 31) << 2;
            float4 vb = *(const float4*)(g_xbc + ((size_t)(bc * CHUNKL + l0 + lr2)) * CONVDIM + DINNER + nc4);
            Bs[lr2][nc4 + 0] = tf32r(vb.x); Bs[lr2][nc4 + 1] = tf32r(vb.y);
            Bs[lr2][nc4 + 2] = tf32r(vb.z); Bs[lr2][nc4 + 3] = tf32r(vb.w);
        }
        __syncthreads();
#pragma unroll
        for (int ks = 0; ks < 2; ks++) {
            int kb = ks * 8;
            unsigned af[4], bf[8][2];
            af[0] = __float_as_uint(As[kb + tig][wm + g]);
            af[1] = __float_as_uint(As[kb + tig][wm + g + 8]);
            af[2] = __float_as_uint(As[kb + tig + 4][wm + g]);
            af[3] = __float_as_uint(As[kb + tig + 4][wm + g + 8]);
#pragma unroll
            for (int nt = 0; nt < 8; nt++) {
                int n = wn + nt * 8;
                bf[nt][0] = __float_as_uint(Bs[kb + tig][n + g]);
                bf[nt][1] = __float_as_uint(Bs[kb + tig + 4][n + g]);
            }
#pragma unroll
            for (int nt = 0; nt < 8; nt++)
                mma_tf32(acc[nt], af, bf[nt]);
        }
        __syncthreads();
    }
    float* sp = g_states + (size_t)bch * HEADDIM * DSTATE;
    int r = wm + g;
#pragma unroll
    for (int nt = 0; nt < 8; nt++) {
        int col = wn + nt * 8 + 2 * tig;
        sp[(size_t)r * DSTATE + col]     = acc[nt][0];
        sp[(size_t)r * DSTATE + col + 1] = acc[nt][1];
        sp[(size_t)(r + 8) * DSTATE + col]     = acc[nt][2];
        sp[(size_t)(r + 8) * DSTATE + col + 1] = acc[nt][3];
    }
}

// ---------------- inter-chunk scan  [__expf] ----------------
__global__ void scan_kernel()
{
    int idx = blockIdx.x * blockDim.x + threadIdx.x;
    if (idx >= BB * NHEADS * HEADDIM * DSTATE) return;
    int n = idx & 127;
    int p = (idx >> 7) & 63;
    int h = (idx >> 13) & 31;
    int b = idx >> 18;
    float carry = 0.f;
    for (int c = 0; c < NC; c++) {
        size_t off = ((size_t)((b * NC + c) * NHEADS + h)) * (HEADDIM * DSTATE) + p * DSTATE + n;
        g_prev[off] = carry;
        float cd = __expf(g_acum[((size_t)(b * NHEADS + h)) * SEQ + c * CHUNKL + CHUNKL - 1]);
        carry = carry * cd + g_states[off];
    }
}

// ---------------- Y = (Y_diag + Y_off + D*xh) * silu(z)  [tf32 mma, __expf] -
__global__ __launch_bounds__(256)
void ydiag_kernel(const float* __restrict__ Dp)
{
    int bch = blockIdx.x;
    int h = bch % NHEADS;
    int bc = bch / NHEADS;
    int b = bc / NC;
    int tid = threadIdx.x;
    int lane = tid & 31, wid = tid >> 5;
    int g = lane >> 2, tig = lane & 3;
    int wm = wid * 32;

    __shared__ float Acs[CHUNKL];
    __shared__ float Gs[16][260];
    __shared__ float Xs[16][68];

    const float* ac = g_acum + ((size_t)(b * NHEADS + h)) * SEQ + (bc % NC) * CHUNKL;
    Acs[tid] = ac[tid];
    __syncthreads();
    float al = Acs[tid];
    float eal = __expf(al);

    float acc[2][8][4];
#pragma unroll
    for (int i = 0; i < 2; i++)
#pragma unroll
        for (int j = 0; j < 8; j++)
#pragma unroll
            for (int v = 0; v < 4; v++) acc[i][j][v] = 0.f;

    const float* Gp = g_G + (size_t)bc * CHUNKL * CHUNKL;

    for (int s0 = 0; s0 < CHUNKL; s0 += 16) {
        float4 gv[4];
#pragma unroll
        for (int q = 0; q < 4; q++)
            gv[q] = *(const float4*)(Gp + (size_t)tid * CHUNKL + s0 + q * 4);
        const float* gf = (const float*)gv;
#pragma unroll
        for (int i = 0; i < 16; i++) {
            int s = s0 + i;
            float v = 0.f;
            if (tid >= s) v = gf[i] * __expf(al - Acs[s]);
            Gs[i][tid] = tf32r(v);
        }
        {
            int lr = tid >> 4, pc = (tid & 15) << 2;
            float4 v4 = *(const float4*)(g_xdt + ((size_t)(bc * CHUNKL + s0 + lr)) * DINNER + h * HEADDIM + pc);
            Xs[lr][pc + 0] = tf32r(v4.x); Xs[lr][pc + 1] = tf32r(v4.y);
            Xs[lr][pc + 2] = tf32r(v4.z); Xs[lr][pc + 3] = tf32r(v4.w);
        }
        __syncthreads();
#pragma unroll
        for (int ks = 0; ks < 2; ks++) {
            int kb = ks * 8;
            unsigned af[2][4], bf[8][2];
#pragma unroll
            for (int mt = 0; mt < 2; mt++) {
                int m = wm + mt * 16;
                af[mt][0] = __float_as_uint(Gs[kb + tig][m + g]);
                af[mt][1] = __float_as_uint(Gs[kb + tig][m + g + 8]);
                af[mt][2] = __float_as_uint(Gs[kb + tig + 4][m + g]);
                af[mt][3] = __float_as_uint(Gs[kb + tig + 4][m + g + 8]);
            }
#pragma unroll
            for (int nt = 0; nt < 8; nt++) {
                int n = nt * 8;
                bf[nt][0] = __float_as_uint(Xs[kb + tig][n + g]);
                bf[nt][1] = __float_as_uint(Xs[kb + tig + 4][n + g]);
            }
#pragma unroll
            for (int mt = 0; mt < 2; mt++)
#pragma unroll
                for (int nt = 0; nt < 8; nt++)
                    mma_tf32(acc[mt][nt], af[mt], bf[nt]);
        }
        __syncthreads();
    }

    const float* pv_base = g_prev + (size_t)bch * HEADDIM * DSTATE;
    for (int n0 = 0; n0 < DSTATE; n0 += 16) {
        float4 cv[4];
#pragma unroll
        for (int q = 0; q < 4; q++)
            cv[q] = *(const float4*)(g_xbc + ((size_t)(bc * CHUNKL + tid)) * CONVDIM + DINNER + DSTATE + n0 + q * 4);
        const float* cf = (const float*)cv;
#pragma unroll
        for (int i = 0; i < 16; i++)
            Gs[i][tid] = tf32r(cf[i] * eal);
        {
            int p = tid >> 2, k4 = (tid & 3) << 2;
            float4 pvv = *(const float4*)(pv_base + (size_t)p * DSTATE + n0 + k4);
            Xs[k4 + 0][p] = tf32r(pvv.x); Xs[k4 + 1][p] = tf32r(pvv.y);
            Xs[k4 + 2][p] = tf32r(pvv.z); Xs[k4 + 3][p] = tf32r(pvv.w);
        }
        __syncthreads();
#pragma unroll
        for (int ks = 0; ks < 2; ks++) {
            int kb = ks * 8;
            unsigned af[2][4], bf[8][2];
#pragma unroll
            for (int mt = 0; mt < 2; mt++) {
                int m = wm + mt * 16;
                af[mt][0] = __float_as_uint(Gs[kb + tig][m + g]);
                af[mt][1] = __float_as_uint(Gs[kb + tig][m + g + 8]);
                af[mt][2] = __float_as_uint(Gs[kb + tig + 4][m + g]);
                af[mt][3] = __float_as_uint(Gs[kb + tig + 4][m + g + 8]);
            }
#pragma unroll
            for (int nt = 0; nt < 8; nt++) {
                int n = nt * 8;
                bf[nt][0] = __float_as_uint(Xs[kb + tig][n + g]);
                bf[nt][1] = __float_as_uint(Xs[kb + tig + 4][n + g]);
            }
#pragma unroll
            for (int mt = 0; mt < 2; mt++)
#pragma unroll
                for (int nt = 0; nt < 8; nt++)
                    mma_tf32(acc[mt][nt], af[mt], bf[nt]);
        }
        __syncthreads();
    }

    float Dh = Dp[h];
#pragma unroll
    for (int mt = 0; mt < 2; mt++) {
        int r0 = wm + mt * 16 + g;
#pragma unroll
        for (int nt = 0; nt < 8; nt++) {
            int pcol = nt * 8 + 2 * tig;
            int d = h * HEADDIM + pcol;
#pragma unroll
            for (int half = 0; half < 2; half++) {
                int l = r0 + half * 8;
                size_t row = (size_t)bc * CHUNKL + l;
                float xh0 = g_xbc[row * CONVDIM + d];
                float xh1 = g_xbc[row * CONVDIM + d + 1];
                float z0 = g_zx[row * DINPROJ + d];
                float z1 = g_zx[row * DINPROJ + d + 1];
                float v0 = acc[mt][nt][half * 2 + 0] + Dh * xh0;
                float v1 = acc[mt][nt][half * 2 + 1] + Dh * xh1;
                v0 *= siluf(z0);
                v1 *= siluf(z1);
                g_y[row * DINNER + d] = v0;
                g_y[row * DINNER + d + 1] = v1;
            }
        }
    }
}

// ---------------- gated RMS norm -> bf16 hi/lo pairs ----------------
__global__ void rms_kernel(const float* __restrict__ rms_w)
{
    int row = blockIdx.x;
    int tid = threadIdx.x;
    const float* y = g_y + (size_t)row * DINNER;
    float ss = 0.f;
    for (int i = tid; i < DINNER; i += 256) { float v = y[i]; ss = fmaf(v, v, ss); }
    __shared__ float red[256];
    red[tid] = ss; __syncthreads();
    for (int o = 128; o > 0; o >>= 1) { if (tid < o) red[tid] += red[tid + o]; __syncthreads(); }
    float scale = rsqrtf(red[0] * (1.f / DINNER) + 1e-12f);
    for (int i = tid * 2; i < DINNER; i += 512) {
        float v0 = y[i] * scale * rms_w[i];
        float v1 = y[i + 1] * scale * rms_w[i + 1];
        unsigned h, l;
        split2(v0, v1, h, l);
        size_t o = (size_t)row * (DINNER / 2) + (i >> 1);
        g_yhi[o] = h; g_ylo[o] = l;
    }
}

// ---------------- residual add + LayerNorm (+ optional bf16 pair output) ----
__global__ void addln_kernel(const float* __restrict__ in1, const float* __restrict__ res,
                             const float* __restrict__ g, const float* __restrict__ bta,
                             float* __restrict__ out,
                             unsigned* __restrict__ ohi, unsigned* __restrict__ olo)
{
    int row = blockIdx.x;
    int tid = threadIdx.x;
    __shared__ float buf[DMODEL];
    __shared__ float red[256];
    float s = 0.f;
    for (int i = tid; i < DMODEL; i += 256) {
        float v = in1[(size_t)row * DMODEL + i] + res[(size_t)row * DMODEL + i];
        buf[i] = v; s += v;
    }
    red[tid] = s; __syncthreads();
    for (int o = 128; o > 0; o >>= 1) { if (tid < o) red[tid] += red[tid + o]; __syncthreads(); }
    float mu = red[0] * (1.f / DMODEL);
    __syncthreads();
    float vs = 0.f;
    for (int i = tid; i < DMODEL; i += 256) { float d = buf[i] - mu; vs = fmaf(d, d, vs); }
    red[tid] = vs; __syncthreads();
    for (int o = 128; o > 0; o >>= 1) { if (tid < o) red[tid] += red[tid + o]; __syncthreads(); }
    float inv = rsqrtf(red[0] * (1.f / DMODEL) + 1e-12f);
    for (int i = tid * 2; i < DMODEL; i += 512) {
        float v0 = (buf[i] - mu) * inv * g[i] + bta[i];
        float v1 = (buf[i + 1] - mu) * inv * g[i + 1] + bta[i + 1];
        out[(size_t)row * DMODEL + i] = v0;
        out[(size_t)row * DMODEL + i + 1] = v1;
        if (ohi) {
            unsigned hh, ll;
            split2(v0, v1, hh, ll);
            size_t o = (size_t)row * (DMODEL / 2) + (i >> 1);
            ohi[o] = hh; olo[o] = ll;
        }
    }
}

// ---------------- launch ----------------
extern "C" void kernel_launch(void* const* d_in, const int* in_sizes, int n_in,
                              void* d_out, int out_size)
{
    const float* x          = (const float*)d_in[0];
    const float* time_diff  = (const float*)d_in[1];
    const float* W_in       = (const float*)d_in[2];
    const float* b_in       = (const float*)d_in[3];
    const float* conv_w     = (const float*)d_in[4];
    const float* conv_b     = (const float*)d_in[5];
    const float* A_log      = (const float*)d_in[6];
    const float* dt_bias    = (const float*)d_in[7];
    const float* Dp         = (const float*)d_in[8];
    const float* time_decay = (const float*)d_in[9];
    const float* rms_w      = (const float*)d_in[10];
    const float* W_out      = (const float*)d_in[11];
    const float* b_out      = (const float*)d_in[12];
    const float* ln_g       = (const float*)d_in[13];
    const float* ln_b       = (const float*)d_in[14];
    const float* fc1_w      = (const float*)d_in[15];
    const float* fc1_b      = (const float*)d_in[16];
    const float* fc2_w      = (const float*)d_in[17];
    const float* fc2_b      = (const float*)d_in[18];
    const float* ln2_g      = (const float*)d_in[19];
    const float* ln2_b      = (const float*)d_in[20];
    float* out = (float*)d_out;

    float *p_zx, *p_hidden, *p_h, *p_ff2;
    cudaGetSymbolAddress((void**)&p_zx, g_zx);
    cudaGetSymbolAddress((void**)&p_hidden, g_hidden);
    cudaGetSymbolAddress((void**)&p_h, g_h);
    cudaGetSymbolAddress((void**)&p_ff2, g_ff2);
    unsigned *p_xhi, *p_xlo, *p_WinT_hi, *p_WinT_lo, *p_WoutT_hi, *p_WoutT_lo;
    unsigned *p_f1T_hi, *p_f1T_lo, *p_f2T_hi, *p_f2T_lo;
    unsigned *p_yhi, *p_ylo, *p_hhi, *p_hlo, *p_ffhi, *p_fflo;
    cudaGetSymbolAddress((void**)&p_xhi, g_xhi);   cudaGetSymbolAddress((void**)&p_xlo, g_xlo);
    cudaGetSymbolAddress((void**)&p_WinT_hi, g_WinT_hi); cudaGetSymbolAddress((void**)&p_WinT_lo, g_WinT_lo);
    cudaGetSymbolAddress((void**)&p_WoutT_hi, g_WoutT_hi); cudaGetSymbolAddress((void**)&p_WoutT_lo, g_WoutT_lo);
    cudaGetSymbolAddress((void**)&p_f1T_hi, g_f1T_hi); cudaGetSymbolAddress((void**)&p_f1T_lo, g_f1T_lo);
    cudaGetSymbolAddress((void**)&p_f2T_hi, g_f2T_hi); cudaGetSymbolAddress((void**)&p_f2T_lo, g_f2T_lo);
    cudaGetSymbolAddress((void**)&p_yhi, g_yhi);   cudaGetSymbolAddress((void**)&p_ylo, g_ylo);
    cudaGetSymbolAddress((void**)&p_hhi, g_hhi);   cudaGetSymbolAddress((void**)&p_hlo, g_hlo);
    cudaGetSymbolAddress((void**)&p_ffhi, g_ffhi); cudaGetSymbolAddress((void**)&p_fflo, g_fflo);

    cudaFuncSetAttribute(gemm_bf, cudaFuncAttributeMaxDynamicSharedMemorySize, GB_SMEM);

    // 1. convert x -> bf16 hi/lo pairs
    convA_kernel<<<(NROWS * DMODEL / 2 + 255) / 256, 256>>>(x, p_xhi, p_xlo, NROWS * DMODEL / 2);
    // 2. convert+transpose W_in
    convBT_kernel<<<dim3(DINPROJ / 32, DMODEL / 32), 256>>>(W_in, p_WinT_hi, p_WinT_lo, DMODEL, DINPROJ);
    // 3. exact fp32 dt_raw
    dtraw_kernel<<<NROWS / 8, 256>>>(x, W_in, b_in);
    // 4. in_proj  [bf16 split, ldmatrix]  (profiled launch)
    gemm_bf<<<dim3((DINPROJ + 127) / 128, NROWS / 128), 256, GB_SMEM>>>(
        p_xhi, p_xlo, p_WinT_hi, p_WinT_lo, b_in, p_zx, (unsigned*)0, (unsigned*)0,
        NROWS, DINPROJ, DMODEL / 2, 0);
    // 5. dt / dA / chunk cumsum
    dtscan_kernel<<<BB * NHEADS * NC, CHUNKL>>>(time_diff, A_log, dt_bias, time_decay);
    // 6. conv + silu + fused xdt
    conv_kernel<<<((NROWS / 4) * CONVDIM + 255) / 256, 256>>>(conv_w, conv_b);
    // 7. G = C @ B^T
    cbgemm_kernel<<<dim3(4, 4, BB * NC), 256>>>();
    // 8. chunk states
    states_kernel<<<BB * NC * NHEADS, 256>>>();
    // 9. inter-chunk scan
    scan_kernel<<<(BB * NHEADS * HEADDIM * DSTATE + 255) / 256, 256>>>();
    // 10. Y
    ydiag_kernel<<<BB * NC * NHEADS, 256>>>(Dp);
    // 11. gated RMS norm -> y hi/lo
    rms_kernel<<<NROWS, 256>>>(rms_w);
    // 12. convert+transpose W_out
    convBT_kernel<<<dim3(DMODEL / 32, DINNER / 32), 256>>>(W_out, p_WoutT_hi, p_WoutT_lo, DINNER, DMODEL);
    // 13. out_proj [bf16 split, ldmatrix]
    gemm_bf<<<dim3(DMODEL / 128, NROWS / 128), 256, GB_SMEM>>>(
        p_yhi, p_ylo, p_WoutT_hi, p_WoutT_lo, b_out, p_hidden, (unsigned*)0, (unsigned*)0,
        NROWS, DMODEL, DINNER / 2, 0);
    // 14. h = LN(hidden + x)  (+ h hi/lo)
    addln_kernel<<<NROWS, 256>>>(p_hidden, x, ln_g, ln_b, p_h, p_hhi, p_hlo);
    // 15. convert+transpose fc1_w
    convBT_kernel<<<dim3(DFF / 32, DMODEL / 32), 256>>>(fc1_w, p_f1T_hi, p_f1T_lo, DMODEL, DFF);
    // 16. fc1 + hardswish [bf16 split, ldmatrix] -> ff hi/lo directly
    gemm_bf<<<dim3(DFF / 128, NROWS / 128), 256, GB_SMEM>>>(
        p_hhi, p_hlo, p_f1T_hi, p_f1T_lo, fc1_b, (float*)0, p_ffhi, p_fflo,
        NROWS, DFF, DMODEL / 2, 1);
    // 17. convert+transpose fc2_w
    convBT_kernel<<<dim3(DMODEL / 32, DFF / 32), 256>>>(fc2_w, p_f2T_hi, p_f2T_lo, DFF, DMODEL);
    // 18. fc2 [bf16 split, ldmatrix]
    gemm_bf<<<dim3(DMODEL / 128, NROWS / 128), 256, GB_SMEM>>>(
        p_ffhi, p_fflo, p_f2T_hi, p_f2T_lo, fc2_b, p_ff2, (unsigned*)0, (unsigned*)0,
        NROWS, DMODEL, DFF / 2, 0);
    // 19. out = LN(ff2 + h)
    addln_kernel<<<NROWS, 256>>>(p_ff2, p_h, ln2_g, ln2_b, out, (unsigned*)0, (unsigned*)0);
    // 20. time_diff passthrough
    cudaMemcpyAsync(out + (size_t)NROWS * DMODEL, time_diff,
                    (size_t)BB * SEQ * sizeof(float), cudaMemcpyDeviceToDevice);
}

// round 14
// speedup vs baseline: 1.3764x; 1.3764x over previous
#include <cuda_runtime.h>
#include <math.h>

// ---------------- problem constants ----------------
#define BB       2
#define SEQ      2048
#define DMODEL   1024
#define DCONV    4
#define HEADDIM  64
#define CHUNKL   256
#define DINNER   2048
#define NHEADS   32
#define CONVDIM  2304   // DINNER + 2*DSTATE
#define DINPROJ  4384   // 2*DINNER + 2*DSTATE + NHEADS
#define DSTATE   128
#define DFF      4096
#define NC       8      // SEQ / CHUNKL
#define NROWS    (BB*SEQ)   // 4096

// ---------------- scratch (device globals; no runtime alloc) ----------------
__device__ float g_zx[(size_t)NROWS*DINPROJ];
__device__ float g_xbc[(size_t)NROWS*CONVDIM];
__device__ float g_xdt[(size_t)NROWS*DINNER];
__device__ float g_dt[(size_t)NROWS*NHEADS];
__device__ float g_draw[(size_t)NROWS*NHEADS];
__device__ float g_acum[(size_t)BB*NHEADS*SEQ];
__device__ float g_G[(size_t)BB*NC*CHUNKL*CHUNKL];
__device__ float g_states[(size_t)BB*NC*NHEADS*HEADDIM*DSTATE];
__device__ float g_prev  [(size_t)BB*NC*NHEADS*HEADDIM*DSTATE];
__device__ float g_y[(size_t)NROWS*DINNER];
__device__ float g_hidden[(size_t)NROWS*DMODEL];
__device__ float g_h[(size_t)NROWS*DMODEL];
__device__ float g_ff[(size_t)NROWS*DFF];
__device__ float g_ff2[(size_t)NROWS*DMODEL];

// ---------------- helpers ----------------
__device__ __forceinline__ float softplusf(float x) {
    return (x > 20.f) ? x : log1pf(expf(x));
}
__device__ __forceinline__ float siluf(float x) {
    return x / (1.f + expf(-x));
}
__device__ __forceinline__ float tf32r(float x) {
    unsigned r;
    asm("cvt.rna.tf32.f32 %0, %1;" : "=r"(r) : "f"(x));
    return __uint_as_float(r);
}
__device__ __forceinline__ unsigned tf32u(float x) {
    unsigned r;
    asm("cvt.rna.tf32.f32 %0, %1;" : "=r"(r) : "f"(x));
    return r;
}
__device__ __forceinline__ unsigned smem_u32(const void* p) {
    unsigned a;
    asm("{ .reg .u64 t; cvta.to.shared.u64 t, %1; cvt.u32.u64 %0, t; }" : "=r"(a) : "l"(p));
    return a;
}
__device__ __forceinline__ void mma_tf32(float* c, const unsigned* a, const unsigned* b) {
    asm volatile("mma.sync.aligned.m16n8k8.row.col.f32.tf32.tf32.f32 "
                 "{%0,%1,%2,%3}, {%4,%5,%6,%7}, {%8,%9}, {%0,%1,%2,%3};"
                 : "+f"(c[0]), "+f"(c[1]), "+f"(c[2]), "+f"(c[3])
                 : "r"(a[0]), "r"(a[1]), "r"(a[2]), "r"(a[3]),
                   "r"(b[0]), "r"(b[1]));
}

// ---------------- cp.async pipelined TF32 GEMM: C = act(A@B+bias) -----------
// CTA tile 128x128, warp tile 32x64, 3-stage pipeline, 2 CTAs/SM.
// Hoisted global/shared address arithmetic: pointers advance by +16 (A)
// and +16*N (B) per issued K16 tile; smem dst offsets are loop-invariant.
#define GSTAGES 3
#define ASTR    20                       // A smem stride (floats): conflict-free
#define BSTR    136                      // B smem stride (floats)
#define A_STF   (128*ASTR)               // 2560 floats per A stage
#define B_STF   (16*BSTR)                // 2176 floats per B stage
#define ST_F    (A_STF + B_STF)          // 4736
#define GT_SMEM (GSTAGES*ST_F*4)         // 56832 bytes

#define GT_ISSUE(stg) do {                                                           \
    unsigned sb = smb + (unsigned)(stg) * (ST_F * 4);                               \
    asm volatile("cp.async.cg.shared.global [%0], [%1], 16;"                        \
                 :: "r"(sb + ad0), "l"(ap0));                                       \
    asm volatile("cp.async.cg.shared.global [%0], [%1], 16;"                        \
                 :: "r"(sb + ad1), "l"(ap1));                                       \
    asm volatile("cp.async.cg.shared.global [%0], [%1], 16, %2;"                    \
                 :: "r"(sb + bd0), "l"(bp0), "r"(bby0));                            \
    asm volatile("cp.async.cg.shared.global [%0], [%1], 16, %2;"                    \
                 :: "r"(sb + bd1), "l"(bp1), "r"(bby1));                            \
    asm volatile("cp.async.commit_group;" ::: "memory");                            \
    ap0 += 16; ap1 += 16;                                                           \
    bp0 += bstep0; bp1 += bstep1;                                                   \
} while (0)

__global__ __launch_bounds__(256, 2)
void gemm_tc(const float* __restrict__ A, const float* __restrict__ B,
             const float* __restrict__ bias, float* __restrict__ C,
             int M, int N, int K, int act)
{
    extern __shared__ float sm[];
    unsigned smb = smem_u32(sm);
    int tid = threadIdx.x;
    int lane = tid & 31, wid = tid >> 5;
    int wm = (wid >> 1) * 32;
    int wn = (wid & 1) * 64;
    int g = lane >> 2, tig = lane & 3;
    int row0 = blockIdx.y * 128, col0 = blockIdx.x * 128;

    // hoisted per-thread load pointers / offsets
    int c0 = tid * 2, c1 = tid * 2 + 1;
    int am0 = c0 >> 2, ak0 = (c0 & 3) << 2;
    int am1 = c1 >> 2, ak1 = (c1 & 3) << 2;
    const float* ap0 = A + (size_t)(row0 + am0) * K + ak0;
    const float* ap1 = A + (size_t)(row0 + am1) * K + ak1;
    unsigned ad0 = (unsigned)(am0 * ASTR + ak0) * 4;
    unsigned ad1 = (unsigned)(am1 * ASTR + ak1) * 4;
    int bk0 = c0 >> 5, bn0 = (c0 & 31) << 2;
    int bk1 = c1 >> 5, bn1 = (c1 & 31) << 2;
    bool bok0 = (col0 + bn0) < N, bok1 = (col0 + bn1) < N;
    const float* bp0 = bok0 ? (B + (size_t)bk0 * N + col0 + bn0) : B;
    const float* bp1 = bok1 ? (B + (size_t)bk1 * N + col0 + bn1) : B;
    int bby0 = bok0 ? 16 : 0, bby1 = bok1 ? 16 : 0;
    size_t bstep0 = bok0 ? (size_t)16 * N : 0;
    size_t bstep1 = bok1 ? (size_t)16 * N : 0;
    unsigned bd0 = (unsigned)(A_STF + bk0 * BSTR + bn0) * 4;
    unsigned bd1 = (unsigned)(A_STF + bk1 * BSTR + bn1) * 4;

    float acc[2][8][4];
#pragma unroll
    for (int i = 0; i < 2; i++)
#pragma unroll
        for (int j = 0; j < 8; j++)
#pragma unroll
            for (int v = 0; v < 4; v++) acc[i][j][v] = 0.f;

    int nt = K / 16;           // >= 64 for all call sites
    GT_ISSUE(0);
    GT_ISSUE(1);

    int stg = 0;               // buffer holding tile t
    int istg = 2;              // next buffer to fill
    for (int t = 0; t < nt; t++) {
        if (t + 2 <= nt) asm volatile("cp.async.wait_group 1;" ::: "memory");
        else             asm volatile("cp.async.wait_group 0;" ::: "memory");
        __syncthreads();
        if (t + 2 < nt) {
            GT_ISSUE(istg);
            istg++; if (istg >= GSTAGES) istg = 0;
        }

        const float* Ab = sm + stg * ST_F;
        const float* Bb = Ab + A_STF;
#pragma unroll
        for (int ks = 0; ks < 2; ks++) {
            int kb = ks * 8;
            unsigned af[2][4], bf[8][2];
#pragma unroll
            for (int mt = 0; mt < 2; mt++) {
                int m = wm + mt * 16;
                af[mt][0] = tf32u(Ab[(m + g) * ASTR + kb + tig]);
                af[mt][1] = tf32u(Ab[(m + g + 8) * ASTR + kb + tig]);
                af[mt][2] = tf32u(Ab[(m + g) * ASTR + kb + tig + 4]);
                af[mt][3] = tf32u(Ab[(m + g + 8) * ASTR + kb + tig + 4]);
            }
#pragma unroll
            for (int nt2 = 0; nt2 < 8; nt2++) {
                int n = wn + nt2 * 8;
                bf[nt2][0] = tf32u(Bb[(kb + tig) * BSTR + n + g]);
                bf[nt2][1] = tf32u(Bb[(kb + tig + 4) * BSTR + n + g]);
            }
#pragma unroll
            for (int mt = 0; mt < 2; mt++)
#pragma unroll
                for (int nt2 = 0; nt2 < 8; nt2++)
                    mma_tf32(acc[mt][nt2], af[mt], bf[nt2]);
        }
        stg++; if (stg >= GSTAGES) stg = 0;
    }

    // epilogue
#pragma unroll
    for (int mt = 0; mt < 2; mt++) {
        int r = row0 + wm + mt * 16 + g;
#pragma unroll
        for (int nt2 = 0; nt2 < 8; nt2++) {
            int col = col0 + wn + nt2 * 8 + 2 * tig;
            if (col < N) {
                float b0 = bias[col], b1 = bias[col + 1];
                float v0 = acc[mt][nt2][0] + b0;
                float v1 = acc[mt][nt2][1] + b1;
                float v2 = acc[mt][nt2][2] + b0;
                float v3 = acc[mt][nt2][3] + b1;
                if (act == 1) {
                    float t;
                    t = fminf(fmaxf(v0 + 3.f, 0.f), 6.f); v0 = v0 * t * (1.f / 6.f);
                    t = fminf(fmaxf(v1 + 3.f, 0.f), 6.f); v1 = v1 * t * (1.f / 6.f);
                    t = fminf(fmaxf(v2 + 3.f, 0.f), 6.f); v2 = v2 * t * (1.f / 6.f);
                    t = fminf(fmaxf(v3 + 3.f, 0.f), 6.f); v3 = v3 * t * (1.f / 6.f);
                }
                C[(size_t)r * N + col] = v0;
                C[(size_t)r * N + col + 1] = v1;
                C[(size_t)(r + 8) * N + col] = v2;
                C[(size_t)(r + 8) * N + col + 1] = v3;
            }
        }
    }
}

// ---------------- exact fp32 dt_raw ----------------
__global__ void dtraw_kernel(const float* __restrict__ x, const float* __restrict__ W_in,
                             const float* __restrict__ b_in)
{
    int row0 = blockIdx.x * 8;
    int tid = threadIdx.x;
    int r = tid >> 5, h = tid & 31;
    __shared__ float xs[8][DMODEL];
    for (int i = tid; i < 8 * DMODEL; i += 256)
        xs[i >> 10][i & 1023] = x[(size_t)(row0 + (i >> 10)) * DMODEL + (i & 1023)];
    __syncthreads();
    const float* wc = W_in + (DINPROJ - NHEADS) + h;
    float a0 = 0.f, a1 = 0.f, a2 = 0.f, a3 = 0.f;
#pragma unroll 2
    for (int k = 0; k < DMODEL; k += 4) {
        a0 = fmaf(xs[r][k + 0], wc[(size_t)(k + 0) * DINPROJ], a0);
        a1 = fmaf(xs[r][k + 1], wc[(size_t)(k + 1) * DINPROJ], a1);
        a2 = fmaf(xs[r][k + 2], wc[(size_t)(k + 2) * DINPROJ], a2);
        a3 = fmaf(xs[r][k + 3], wc[(size_t)(k + 3) * DINPROJ], a3);
    }
    g_draw[(size_t)(row0 + r) * NHEADS + h] =
        b_in[DINPROJ - NHEADS + h] + ((a0 + a1) + (a2 + a3));
}

// ---------------- conv + silu + fused xdt (4 seq positions / thread) --------
__global__ void conv_kernel(const float* __restrict__ conv_w, const float* __restrict__ conv_b)
{
    int idx = blockIdx.x * blockDim.x + threadIdx.x;
    if (idx >= (NROWS / 4) * CONVDIM) return;
    int ch = idx % CONVDIM;
    int rg = idx / CONVDIM;
    int row0 = rg * 4;
    int l0 = row0 % SEQ;
    float w0 = conv_w[ch * DCONV + 0], w1 = conv_w[ch * DCONV + 1];
    float w2 = conv_w[ch * DCONV + 2], w3 = conv_w[ch * DCONV + 3];
    float bv = conv_b[ch];
    float v[7];
#pragma unroll
    for (int j = 0; j < 7; j++) {
        int l = l0 + j - 3;
        v[j] = (l >= 0) ? g_zx[(size_t)(row0 + j - 3) * DINPROJ + DINNER + ch] : 0.f;
    }
#pragma unroll
    for (int i = 0; i < 4; i++) {
        float a = bv;
        a = fmaf(v[i], w0, a);
        a = fmaf(v[i + 1], w1, a);
        a = fmaf(v[i + 2], w2, a);
        a = fmaf(v[i + 3], w3, a);
        float o = siluf(a);
        size_t row = row0 + i;
        g_xbc[row * CONVDIM + ch] = o;
        if (ch < DINNER)
            g_xdt[row * DINNER + ch] = o * g_dt[row * NHEADS + (ch >> 6)];
    }
}

// ---------------- dt / dA + per-chunk inclusive cumsum (exact exp) ----------
__global__ void dtscan_kernel(const float* __restrict__ tdiff,
                              const float* __restrict__ A_log,
                              const float* __restrict__ dt_bias,
                              const float* __restrict__ time_decay)
{
    int blk = blockIdx.x;
    int c = blk % NC;
    int h = (blk / NC) % NHEADS;
    int b = blk / (NC * NHEADS);
    int l = threadIdx.x;
    __shared__ float s[CHUNKL];
    int row = b * SEQ + c * CHUNKL + l;
    float draw = g_draw[(size_t)row * NHEADS + h];
    float dt = softplusf(draw + dt_bias[h]);
    float Ah = -expf(A_log[h]);
    float spd = softplusf(time_decay[h]);
    float dA = dt * Ah - spd * tdiff[row];
    g_dt[(size_t)row * NHEADS + h] = dt;
    s[l] = dA;
    __syncthreads();
    for (int off = 1; off < CHUNKL; off <<= 1) {
        float v = (l >= off) ? s[l - off] : 0.f;
        __syncthreads();
        s[l] += v;
        __syncthreads();
    }
    g_acum[((size_t)(b * NHEADS + h)) * SEQ + c * CHUNKL + l] = s[l];
}

// ---------------- G = C @ B^T per (b,chunk)  [tf32 mma, 64x64 tiles] --------
__global__ __launch_bounds__(256)
void cbgemm_kernel()
{
    int bc = blockIdx.z;
    int l0 = blockIdx.y * 64, s0 = blockIdx.x * 64;
    __shared__ float As[16][72];
    __shared__ float Bs2[16][72];
    int tid = threadIdx.x;
    int lane = tid & 31, wid = tid >> 5;
    int wm = (wid & 3) * 16;
    int wn = (wid >> 2) * 32;
    int g = lane >> 2, tig = lane & 3;

    float acc[4][4];
#pragma unroll
    for (int j = 0; j < 4; j++)
#pragma unroll
        for (int v = 0; v < 4; v++) acc[j][v] = 0.f;

    const float* base = g_xbc + (size_t)bc * CHUNKL * CONVDIM;
    int r = tid >> 2, c4 = (tid & 3) << 2;
    for (int n0 = 0; n0 < DSTATE; n0 += 16) {
        float4 vc = *(const float4*)(base + (size_t)(l0 + r) * CONVDIM + DINNER + DSTATE + n0 + c4);
        As[c4 + 0][r] = tf32r(vc.x); As[c4 + 1][r] = tf32r(vc.y);
        As[c4 + 2][r] = tf32r(vc.z); As[c4 + 3][r] = tf32r(vc.w);
        float4 vb = *(const float4*)(base + (size_t)(s0 + r) * CONVDIM + DINNER + n0 + c4);
        Bs2[c4 + 0][r] = tf32r(vb.x); Bs2[c4 + 1][r] = tf32r(vb.y);
        Bs2[c4 + 2][r] = tf32r(vb.z); Bs2[c4 + 3][r] = tf32r(vb.w);
        __syncthreads();
#pragma unroll
        for (int ks = 0; ks < 2; ks++) {
            int kb = ks * 8;
            unsigned af[4], bf[4][2];
            af[0] = __float_as_uint(As[kb + tig][wm + g]);
            af[1] = __float_as_uint(As[kb + tig][wm + g + 8]);
            af[2] = __float_as_uint(As[kb + tig + 4][wm + g]);
            af[3] = __float_as_uint(As[kb + tig + 4][wm + g + 8]);
#pragma unroll
            for (int nt = 0; nt < 4; nt++) {
                int n = wn + nt * 8;
                bf[nt][0] = __float_as_uint(Bs2[kb + tig][n + g]);
                bf[nt][1] = __float_as_uint(Bs2[kb + tig + 4][n + g]);
            }
#pragma unroll
            for (int nt = 0; nt < 4; nt++)
                mma_tf32(acc[nt], af, bf[nt]);
        }
        __syncthreads();
    }
    float* Gp = g_G + (size_t)bc * CHUNKL * CHUNKL;
    int rr = l0 + wm + g;
#pragma unroll
    for (int nt = 0; nt < 4; nt++) {
        int col = s0 + wn + nt * 8 + 2 * tig;
        Gp[(size_t)rr * CHUNKL + col]     = acc[nt][0];
        Gp[(size_t)rr * CHUNKL + col + 1] = acc[nt][1];
        Gp[(size_t)(rr + 8) * CHUNKL + col]     = acc[nt][2];
        Gp[(size_t)(rr + 8) * CHUNKL + col + 1] = acc[nt][3];
    }
}

// ---------------- chunk states  [tf32 mma, __expf] ----------------
__global__ __launch_bounds__(256)
void states_kernel()
{
    int bch = blockIdx.x;
    int h = bch % NHEADS;
    int bc = bch / NHEADS;
    int b = bc / NC, c = bc % NC;
    int tid = threadIdx.x;
    int lane = tid & 31, wid = tid >> 5;
    int wm = (wid >> 1) * 16;
    int wn = (wid & 1) * 64;
    int g = lane >> 2, tig = lane & 3;

    __shared__ float w[CHUNKL];
    __shared__ float As[16][72];
    __shared__ float Bs[16][136];
    const float* ac = g_acum + ((size_t)(b * NHEADS + h)) * SEQ + c * CHUNKL;
    w[tid] = __expf(ac[CHUNKL - 1] - ac[tid]);
    __syncthreads();

    float acc[8][4];
#pragma unroll
    for (int j = 0; j < 8; j++)
#pragma unroll
        for (int v = 0; v < 4; v++) acc[j][v] = 0.f;

    for (int l0 = 0; l0 < CHUNKL; l0 += 16) {
        {
            int lr = tid >> 4, pc = (tid & 15) << 2;
            float4 v = *(const float4*)(g_xdt + ((size_t)(bc * CHUNKL + l0 + lr)) * DINNER + h * HEADDIM + pc);
            float ww = w[l0 + lr];
            As[lr][pc + 0] = tf32r(v.x * ww); As[lr][pc + 1] = tf32r(v.y * ww);
            As[lr][pc + 2] = tf32r(v.z * ww); As[lr][pc + 3] = tf32r(v.w * ww);
        }
#pragma unroll
        for (int u = 0; u < 2; u++) {
            int id = tid * 2 + u;
            int lr2 = id >> 5, nc4 = (id & 31) << 2;
            float4 vb = *(const float4*)(g_xbc + ((size_t)(bc * CHUNKL + l0 + lr2)) * CONVDIM + DINNER + nc4);
            Bs[lr2][nc4 + 0] = tf32r(vb.x); Bs[lr2][nc4 + 1] = tf32r(vb.y);
            Bs[lr2][nc4 + 2] = tf32r(vb.z); Bs[lr2][nc4 + 3] = tf32r(vb.w);
        }
        __syncthreads();
#pragma unroll
        for (int ks = 0; ks < 2; ks++) {
            int kb = ks * 8;
            unsigned af[4], bf[8][2];
            af[0] = __float_as_uint(As[kb + tig][wm + g]);
            af[1] = __float_as_uint(As[kb + tig][wm + g + 8]);
            af[2] = __float_as_uint(As[kb + tig + 4][wm + g]);
            af[3] = __float_as_uint(As[kb + tig + 4][wm + g + 8]);
#pragma unroll
            for (int nt = 0; nt < 8; nt++) {
                int n = wn + nt * 8;
                bf[nt][0] = __float_as_uint(Bs[kb + tig][n + g]);
                bf[nt][1] = __float_as_uint(Bs[kb + tig + 4][n + g]);
            }
#pragma unroll
            for (int nt = 0; nt < 8; nt++)
                mma_tf32(acc[nt], af, bf[nt]);
        }
        __syncthreads();
    }
    float* sp = g_states + (size_t)bch * HEADDIM * DSTATE;
    int r = wm + g;
#pragma unroll
    for (int nt = 0; nt < 8; nt++) {
        int col = wn + nt * 8 + 2 * tig;
        sp[(size_t)r * DSTATE + col]     = acc[nt][0];
        sp[(size_t)r * DSTATE + col + 1] = acc[nt][1];
        sp[(size_t)(r + 8) * DSTATE + col]     = acc[nt][2];
        sp[(size_t)(r + 8) * DSTATE + col + 1] = acc[nt][3];
    }
}

// ---------------- inter-chunk scan  [__expf] ----------------
__global__ void scan_kernel()
{
    int idx = blockIdx.x * blockDim.x + threadIdx.x;
    if (idx >= BB * NHEADS * HEADDIM * DSTATE) return;
    int n = idx & 127;
    int p = (idx >> 7) & 63;
    int h = (idx >> 13) & 31;
    int b = idx >> 18;
    float carry = 0.f;
    for (int c = 0; c < NC; c++) {
        size_t off = ((size_t)((b * NC + c) * NHEADS + h)) * (HEADDIM * DSTATE) + p * DSTATE + n;
        g_prev[off] = carry;
        float cd = __expf(g_acum[((size_t)(b * NHEADS + h)) * SEQ + c * CHUNKL + CHUNKL - 1]);
        carry = carry * cd + g_states[off];
    }
}

// ---------------- Y = (Y_diag + Y_off + D*xh) * silu(z)  [tf32 mma, __expf] -
__global__ __launch_bounds__(256)
void ydiag_kernel(const float* __restrict__ Dp)
{
    int bch = blockIdx.x;
    int h = bch % NHEADS;
    int bc = bch / NHEADS;
    int b = bc / NC;
    int tid = threadIdx.x;
    int lane = tid & 31, wid = tid >> 5;
    int g = lane >> 2, tig = lane & 3;
    int wm = wid * 32;

    __shared__ float Acs[CHUNKL];
    __shared__ float Gs[16][260];
    __shared__ float Xs[16][68];

    const float* ac = g_acum + ((size_t)(b * NHEADS + h)) * SEQ + (bc % NC) * CHUNKL;
    Acs[tid] = ac[tid];
    __syncthreads();
    float al = Acs[tid];
    float eal = __expf(al);

    float acc[2][8][4];
#pragma unroll
    for (int i = 0; i < 2; i++)
#pragma unroll
        for (int j = 0; j < 8; j++)
#pragma unroll
            for (int v = 0; v < 4; v++) acc[i][j][v] = 0.f;

    const float* Gp = g_G + (size_t)bc * CHUNKL * CHUNKL;

    for (int s0 = 0; s0 < CHUNKL; s0 += 16) {
        float4 gv[4];
#pragma unroll
        for (int q = 0; q < 4; q++)
            gv[q] = *(const float4*)(Gp + (size_t)tid * CHUNKL + s0 + q * 4);
        const float* gf = (const float*)gv;
#pragma unroll
        for (int i = 0; i < 16; i++) {
            int s = s0 + i;
            float v = 0.f;
            if (tid >= s) v = gf[i] * __expf(al - Acs[s]);
            Gs[i][tid] = tf32r(v);
        }
        {
            int lr = tid >> 4, pc = (tid & 15) << 2;
            float4 v4 = *(const float4*)(g_xdt + ((size_t)(bc * CHUNKL + s0 + lr)) * DINNER + h * HEADDIM + pc);
            Xs[lr][pc + 0] = tf32r(v4.x); Xs[lr][pc + 1] = tf32r(v4.y);
            Xs[lr][pc + 2] = tf32r(v4.z); Xs[lr][pc + 3] = tf32r(v4.w);
        }
        __syncthreads();
#pragma unroll
        for (int ks = 0; ks < 2; ks++) {
            int kb = ks * 8;
            unsigned af[2][4], bf[8][2];
#pragma unroll
            for (int mt = 0; mt < 2; mt++) {
                int m = wm + mt * 16;
                af[mt][0] = __float_as_uint(Gs[kb + tig][m + g]);
                af[mt][1] = __float_as_uint(Gs[kb + tig][m + g + 8]);
                af[mt][2] = __float_as_uint(Gs[kb + tig + 4][m + g]);
                af[mt][3] = __float_as_uint(Gs[kb + tig + 4][m + g + 8]);
            }
#pragma unroll
            for (int nt = 0; nt < 8; nt++) {
                int n = nt * 8;
                bf[nt][0] = __float_as_uint(Xs[kb + tig][n + g]);
                bf[nt][1] = __float_as_uint(Xs[kb + tig + 4][n + g]);
            }
#pragma unroll
            for (int mt = 0; mt < 2; mt++)
#pragma unroll
                for (int nt = 0; nt < 8; nt++)
                    mma_tf32(acc[mt][nt], af[mt], bf[nt]);
        }
        __syncthreads();
    }

    const float* pv_base = g_prev + (size_t)bch * HEADDIM * DSTATE;
    for (int n0 = 0; n0 < DSTATE; n0 += 16) {
        float4 cv[4];
#pragma unroll
        for (int q = 0; q < 4; q++)
            cv[q] = *(const float4*)(g_xbc + ((size_t)(bc * CHUNKL + tid)) * CONVDIM + DINNER + DSTATE + n0 + q * 4);
        const float* cf = (const float*)cv;
#pragma unroll
        for (int i = 0; i < 16; i++)
            Gs[i][tid] = tf32r(cf[i] * eal);
        {
            int p = tid >> 2, k4 = (tid & 3) << 2;
            float4 pvv = *(const float4*)(pv_base + (size_t)p * DSTATE + n0 + k4);
            Xs[k4 + 0][p] = tf32r(pvv.x); Xs[k4 + 1][p] = tf32r(pvv.y);
            Xs[k4 + 2][p] = tf32r(pvv.z); Xs[k4 + 3][p] = tf32r(pvv.w);
        }
        __syncthreads();
#pragma unroll
        for (int ks = 0; ks < 2; ks++) {
            int kb = ks * 8;
            unsigned af[2][4], bf[8][2];
#pragma unroll
            for (int mt = 0; mt < 2; mt++) {
                int m = wm + mt * 16;
                af[mt][0] = __float_as_uint(Gs[kb + tig][m + g]);
                af[mt][1] = __float_as_uint(Gs[kb + tig][m + g + 8]);
                af[mt][2] = __float_as_uint(Gs[kb + tig + 4][m + g]);
                af[mt][3] = __float_as_uint(Gs[kb + tig + 4][m + g + 8]);
            }
#pragma unroll
            for (int nt = 0; nt < 8; nt++) {
                int n = nt * 8;
                bf[nt][0] = __float_as_uint(Xs[kb + tig][n + g]);
                bf[nt][1] = __float_as_uint(Xs[kb + tig + 4][n + g]);
            }
#pragma unroll
            for (int mt = 0; mt < 2; mt++)
#pragma unroll
                for (int nt = 0; nt < 8; nt++)
                    mma_tf32(acc[mt][nt], af[mt], bf[nt]);
        }
        __syncthreads();
    }

    float Dh = Dp[h];
#pragma unroll
    for (int mt = 0; mt < 2; mt++) {
        int r0 = wm + mt * 16 + g;
#pragma unroll
        for (int nt = 0; nt < 8; nt++) {
            int pcol = nt * 8 + 2 * tig;
            int d = h * HEADDIM + pcol;
#pragma unroll
            for (int half = 0; half < 2; half++) {
                int l = r0 + half * 8;
                size_t row = (size_t)bc * CHUNKL + l;
                float xh0 = g_xbc[row * CONVDIM + d];
                float xh1 = g_xbc[row * CONVDIM + d + 1];
                float z0 = g_zx[row * DINPROJ + d];
                float z1 = g_zx[row * DINPROJ + d + 1];
                float v0 = acc[mt][nt][half * 2 + 0] + Dh * xh0;
                float v1 = acc[mt][nt][half * 2 + 1] + Dh * xh1;
                v0 *= siluf(z0);
                v1 *= siluf(z1);
                g_y[row * DINNER + d] = v0;
                g_y[row * DINNER + d + 1] = v1;
            }
        }
    }
}

// ---------------- gated RMS norm ----------------
__global__ void rms_kernel(const float* __restrict__ rms_w)
{
    int row = blockIdx.x;
    int tid = threadIdx.x;
    float* y = g_y + (size_t)row * DINNER;
    float ss = 0.f;
    for (int i = tid; i < DINNER; i += 256) { float v = y[i]; ss = fmaf(v, v, ss); }
    __shared__ float red[256];
    red[tid] = ss; __syncthreads();
    for (int o = 128; o > 0; o >>= 1) { if (tid < o) red[tid] += red[tid + o]; __syncthreads(); }
    float scale = rsqrtf(red[0] * (1.f / DINNER) + 1e-12f);
    for (int i = tid; i < DINNER; i += 256) y[i] = y[i] * scale * rms_w[i];
}

// ---------------- residual add + LayerNorm ----------------
__global__ void addln_kernel(const float* __restrict__ in1, const float* __restrict__ res,
                             const float* __restrict__ g, const float* __restrict__ bta,
                             float* __restrict__ out)
{
    int row = blockIdx.x;
    int tid = threadIdx.x;
    __shared__ float buf[DMODEL];
    __shared__ float red[256];
    float s = 0.f;
    for (int i = tid; i < DMODEL; i += 256) {
        float v = in1[(size_t)row * DMODEL + i] + res[(size_t)row * DMODEL + i];
        buf[i] = v; s += v;
    }
    red[tid] = s; __syncthreads();
    for (int o = 128; o > 0; o >>= 1) { if (tid < o) red[tid] += red[tid + o]; __syncthreads(); }
    float mu = red[0] * (1.f / DMODEL);
    __syncthreads();
    float vs = 0.f;
    for (int i = tid; i < DMODEL; i += 256) { float d = buf[i] - mu; vs = fmaf(d, d, vs); }
    red[tid] = vs; __syncthreads();
    for (int o = 128; o > 0; o >>= 1) { if (tid < o) red[tid] += red[tid + o]; __syncthreads(); }
    float inv = rsqrtf(red[0] * (1.f / DMODEL) + 1e-12f);
    for (int i = tid; i < DMODEL; i += 256)
        out[(size_t)row * DMODEL + i] = (buf[i] - mu) * inv * g[i] + bta[i];
}

// ---------------- launch ----------------
extern "C" void kernel_launch(void* const* d_in, const int* in_sizes, int n_in,
                              void* d_out, int out_size)
{
    const float* x          = (const float*)d_in[0];
    const float* time_diff  = (const float*)d_in[1];
    const float* W_in       = (const float*)d_in[2];
    const float* b_in       = (const float*)d_in[3];
    const float* conv_w     = (const float*)d_in[4];
    const float* conv_b     = (const float*)d_in[5];
    const float* A_log      = (const float*)d_in[6];
    const float* dt_bias    = (const float*)d_in[7];
    const float* Dp         = (const float*)d_in[8];
    const float* time_decay = (const float*)d_in[9];
    const float* rms_w      = (const float*)d_in[10];
    const float* W_out      = (const float*)d_in[11];
    const float* b_out      = (const float*)d_in[12];
    const float* ln_g       = (const float*)d_in[13];
    const float* ln_b       = (const float*)d_in[14];
    const float* fc1_w      = (const float*)d_in[15];
    const float* fc1_b      = (const float*)d_in[16];
    const float* fc2_w      = (const float*)d_in[17];
    const float* fc2_b      = (const float*)d_in[18];
    const float* ln2_g      = (const float*)d_in[19];
    const float* ln2_b      = (const float*)d_in[20];
    float* out = (float*)d_out;

    float *p_zx, *p_y, *p_hidden, *p_h, *p_ff, *p_ff2;
    cudaGetSymbolAddress((void**)&p_zx, g_zx);
    cudaGetSymbolAddress((void**)&p_y, g_y);
    cudaGetSymbolAddress((void**)&p_hidden, g_hidden);
    cudaGetSymbolAddress((void**)&p_h, g_h);
    cudaGetSymbolAddress((void**)&p_ff, g_ff);
    cudaGetSymbolAddress((void**)&p_ff2, g_ff2);

    cudaFuncSetAttribute(gemm_tc, cudaFuncAttributeMaxDynamicSharedMemorySize, GT_SMEM);

    // 1. in_proj
    gemm_tc<<<dim3((DINPROJ + 127) / 128, NROWS / 128), 256, GT_SMEM>>>(
        x, W_in, b_in, p_zx, NROWS, DINPROJ, DMODEL, 0);
    // 1b. exact fp32 dt_raw
    dtraw_kernel<<<NROWS / 8, 256>>>(x, W_in, b_in);
    // 2. dt / dA / chunk cumsum
    dtscan_kernel<<<BB * NHEADS * NC, CHUNKL>>>(time_diff, A_log, dt_bias, time_decay);
    // 3. conv + silu + fused xdt
    conv_kernel<<<((NROWS / 4) * CONVDIM + 255) / 256, 256>>>(conv_w, conv_b);
    // 4. G = C @ B^T  [tf32, 64x64]
    cbgemm_kernel<<<dim3(4, 4, BB * NC), 256>>>();
    // 5. chunk states [tf32, __expf]
    states_kernel<<<BB * NC * NHEADS, 256>>>();
    // 6. inter-chunk scan [__expf]
    scan_kernel<<<(BB * NHEADS * HEADDIM * DSTATE + 255) / 256, 256>>>();
    // 7. Y [tf32, __expf]
    ydiag_kernel<<<BB * NC * NHEADS, 256>>>(Dp);
    // 8. gated RMS norm
    rms_kernel<<<NROWS, 256>>>(rms_w);
    // 9. out_proj
    gemm_tc<<<dim3(DMODEL / 128, NROWS / 128), 256, GT_SMEM>>>(
        p_y, W_out, b_out, p_hidden, NROWS, DMODEL, DINNER, 0);
    // 10. h = LN(hidden + x)
    addln_kernel<<<NROWS, 256>>>(p_hidden, x, ln_g, ln_b, p_h);
    // 11. fc1 + hardswish
    gemm_tc<<<dim3(DFF / 128, NROWS / 128), 256, GT_SMEM>>>(
        p_h, fc1_w, fc1_b, p_ff, NROWS, DFF, DMODEL, 1);
    // 12. fc2
    gemm_tc<<<dim3(DMODEL / 128, NROWS / 128), 256, GT_SMEM>>>(
        p_ff, fc2_w, fc2_b, p_ff2, NROWS, DMODEL, DFF, 0);
    // 13. out = LN(ff2 + h)
    addln_kernel<<<NROWS, 256>>>(p_ff2, p_h, ln2_g, ln2_b, out);
    // 14. time_diff passthrough
    cudaMemcpyAsync(out + (size_t)NROWS * DMODEL, time_diff,
                    (size_t)BB * SEQ * sizeof(float), cudaMemcpyDeviceToDevice);
}

// round 15
// speedup vs baseline: 1.4744x; 1.0712x over previous
#include <cuda_runtime.h>
#include <math.h>

// ---------------- problem constants ----------------
#define BB       2
#define SEQ      2048
#define DMODEL   1024
#define DCONV    4
#define HEADDIM  64
#define CHUNKL   256
#define DINNER   2048
#define NHEADS   32
#define CONVDIM  2304   // DINNER + 2*DSTATE
#define DINPROJ  4384   // 2*DINNER + 2*DSTATE + NHEADS
#define DSTATE   128
#define DFF      4096
#define NC       8      // SEQ / CHUNKL
#define NROWS    (BB*SEQ)   // 4096

// ---------------- scratch (device globals; no runtime alloc) ----------------
__device__ float g_zx[(size_t)NROWS*DINPROJ];
__device__ float g_xbc[(size_t)NROWS*CONVDIM];
__device__ float g_xdt[(size_t)NROWS*DINNER];
__device__ float g_dt[(size_t)NROWS*NHEADS];
__device__ float g_draw[(size_t)NROWS*NHEADS];
__device__ float g_acum[(size_t)BB*NHEADS*SEQ];
__device__ float g_G[(size_t)BB*NC*CHUNKL*CHUNKL];
__device__ float g_states[(size_t)BB*NC*NHEADS*HEADDIM*DSTATE];
__device__ float g_prev  [(size_t)BB*NC*NHEADS*HEADDIM*DSTATE];
__device__ float g_y[(size_t)NROWS*DINNER];
__device__ float g_hidden[(size_t)NROWS*DMODEL];
__device__ float g_h[(size_t)NROWS*DMODEL];
__device__ float g_ff[(size_t)NROWS*DFF];
__device__ float g_ff2[(size_t)NROWS*DMODEL];

// ---------------- helpers ----------------
__device__ __forceinline__ float softplusf(float x) {
    return (x > 20.f) ? x : log1pf(expf(x));
}
__device__ __forceinline__ float siluf(float x) {
    return x / (1.f + expf(-x));
}
__device__ __forceinline__ float tf32r(float x) {
    unsigned r;
    asm("cvt.rna.tf32.f32 %0, %1;" : "=r"(r) : "f"(x));
    return __uint_as_float(r);
}
__device__ __forceinline__ unsigned tf32u(float x) {
    unsigned r;
    asm("cvt.rna.tf32.f32 %0, %1;" : "=r"(r) : "f"(x));
    return r;
}
__device__ __forceinline__ unsigned smem_u32(const void* p) {
    unsigned a;
    asm("{ .reg .u64 t; cvta.to.shared.u64 t, %1; cvt.u32.u64 %0, t; }" : "=r"(a) : "l"(p));
    return a;
}
__device__ __forceinline__ void mma_tf32(float* c, const unsigned* a, const unsigned* b) {
    asm volatile("mma.sync.aligned.m16n8k8.row.col.f32.tf32.tf32.f32 "
                 "{%0,%1,%2,%3}, {%4,%5,%6,%7}, {%8,%9}, {%0,%1,%2,%3};"
                 : "+f"(c[0]), "+f"(c[1]), "+f"(c[2]), "+f"(c[3])
                 : "r"(a[0]), "r"(a[1]), "r"(a[2]), "r"(a[3]),
                   "r"(b[0]), "r"(b[1]));
}
// block reduction over 256 threads (8 warps) via shuffles, 1 barrier
__device__ __forceinline__ float block_sum256(float v, float* red8, int tid) {
#pragma unroll
    for (int o = 16; o > 0; o >>= 1)
        v += __shfl_down_sync(0xffffffffu, v, o);
    if ((tid & 31) == 0) red8[tid >> 5] = v;
    __syncthreads();
    float s = (tid < 8) ? red8[tid] : 0.f;
#pragma unroll
    for (int o = 4; o > 0; o >>= 1)
        s += __shfl_down_sync(0xffu, s, o);
    return __shfl_sync(0xffffffffu, s, 0, 32);   // valid in warp 0
}

// ---------------- cp.async pipelined TF32 GEMM: C = act(A@B+bias) -----------
// CTA tile 128x128, warp tile 32x64, 3-stage pipeline, 2 CTAs/SM.  (R10 champion)
#define GSTAGES 3
#define ASTR    20                       // A smem stride (floats): conflict-free
#define BSTR    136                      // B smem stride (floats)
#define A_STF   (128*ASTR)               // 2560 floats per A stage
#define B_STF   (16*BSTR)                // 2176 floats per B stage
#define ST_F    (A_STF + B_STF)          // 4736
#define GT_SMEM (GSTAGES*ST_F*4)         // 56832 bytes

#define GT_ISSUE(stg, kt) do {                                                      \
    unsigned sb = smb + (unsigned)(stg) * (ST_F * 4);                               \
    unsigned bbs = sb + A_STF * 4;                                                  \
    int k0i = (kt) * 16;                                                            \
    _Pragma("unroll")                                                               \
    for (int u = 0; u < 2; u++) {                                                   \
        int c = tid * 2 + u;                                                        \
        int m = c >> 2, kq = (c & 3) << 2;                                          \
        const float* sp = A + (size_t)(row0 + m) * K + k0i + kq;                    \
        asm volatile("cp.async.cg.shared.global [%0], [%1], 16;"                    \
                     :: "r"(sb + (unsigned)(m * ASTR + kq) * 4), "l"(sp));          \
        int kk = c >> 5, nq = (c & 31) << 2;                                        \
        int gc = col0 + nq;                                                         \
        const float* sp2 = (gc < N) ? (B + (size_t)(k0i + kk) * N + gc) : B;        \
        int by = (gc < N) ? 16 : 0;                                                 \
        asm volatile("cp.async.cg.shared.global [%0], [%1], 16, %2;"                \
                     :: "r"(bbs + (unsigned)(kk * BSTR + nq) * 4), "l"(sp2), "r"(by)); \
    }                                                                               \
    asm volatile("cp.async.commit_group;" ::: "memory");                            \
} while (0)

__global__ __launch_bounds__(256, 2)
void gemm_tc(const float* __restrict__ A, const float* __restrict__ B,
             const float* __restrict__ bias, float* __restrict__ C,
             int M, int N, int K, int act)
{
    extern __shared__ float sm[];
    unsigned smb = smem_u32(sm);
    int tid = threadIdx.x;
    int lane = tid & 31, wid = tid >> 5;
    int wm = (wid >> 1) * 32;
    int wn = (wid & 1) * 64;
    int g = lane >> 2, tig = lane & 3;
    int row0 = blockIdx.y * 128, col0 = blockIdx.x * 128;

    float acc[2][8][4];
#pragma unroll
    for (int i = 0; i < 2; i++)
#pragma unroll
        for (int j = 0; j < 8; j++)
#pragma unroll
            for (int v = 0; v < 4; v++) acc[i][j][v] = 0.f;

    int nt = K / 16;           // >= 64 for all call sites
    GT_ISSUE(0, 0);
    GT_ISSUE(1, 1);

    int stg = 0;               // buffer holding tile t
    for (int t = 0; t < nt; t++) {
        if (t + 2 <= nt) asm volatile("cp.async.wait_group 1;" ::: "memory");
        else             asm volatile("cp.async.wait_group 0;" ::: "memory");
        __syncthreads();
        if (t + 2 < nt) {
            int nstg = stg + 2; if (nstg >= GSTAGES) nstg -= GSTAGES;
            GT_ISSUE(nstg, t + 2);
        }

        const float* Ab = sm + stg * ST_F;
        const float* Bb = Ab + A_STF;
#pragma unroll
        for (int ks = 0; ks < 2; ks++) {
            int kb = ks * 8;
            unsigned af[2][4], bf[8][2];
#pragma unroll
            for (int mt = 0; mt < 2; mt++) {
                int m = wm + mt * 16;
                af[mt][0] = tf32u(Ab[(m + g) * ASTR + kb + tig]);
                af[mt][1] = tf32u(Ab[(m + g + 8) * ASTR + kb + tig]);
                af[mt][2] = tf32u(Ab[(m + g) * ASTR + kb + tig + 4]);
                af[mt][3] = tf32u(Ab[(m + g + 8) * ASTR + kb + tig + 4]);
            }
#pragma unroll
            for (int nt2 = 0; nt2 < 8; nt2++) {
                int n = wn + nt2 * 8;
                bf[nt2][0] = tf32u(Bb[(kb + tig) * BSTR + n + g]);
                bf[nt2][1] = tf32u(Bb[(kb + tig + 4) * BSTR + n + g]);
            }
#pragma unroll
            for (int mt = 0; mt < 2; mt++)
#pragma unroll
                for (int nt2 = 0; nt2 < 8; nt2++)
                    mma_tf32(acc[mt][nt2], af[mt], bf[nt2]);
        }
        stg++; if (stg >= GSTAGES) stg = 0;
    }

    // epilogue
#pragma unroll
    for (int mt = 0; mt < 2; mt++) {
        int r = row0 + wm + mt * 16 + g;
#pragma unroll
        for (int nt2 = 0; nt2 < 8; nt2++) {
            int col = col0 + wn + nt2 * 8 + 2 * tig;
            if (col < N) {
                float b0 = bias[col], b1 = bias[col + 1];
                float v0 = acc[mt][nt2][0] + b0;
                float v1 = acc[mt][nt2][1] + b1;
                float v2 = acc[mt][nt2][2] + b0;
                float v3 = acc[mt][nt2][3] + b1;
                if (act == 1) {
                    float t;
                    t = fminf(fmaxf(v0 + 3.f, 0.f), 6.f); v0 = v0 * t * (1.f / 6.f);
                    t = fminf(fmaxf(v1 + 3.f, 0.f), 6.f); v1 = v1 * t * (1.f / 6.f);
                    t = fminf(fmaxf(v2 + 3.f, 0.f), 6.f); v2 = v2 * t * (1.f / 6.f);
                    t = fminf(fmaxf(v3 + 3.f, 0.f), 6.f); v3 = v3 * t * (1.f / 6.f);
                }
                C[(size_t)r * N + col] = v0;
                C[(size_t)r * N + col + 1] = v1;
                C[(size_t)(r + 8) * N + col] = v2;
                C[(size_t)(r + 8) * N + col + 1] = v3;
            }
        }
    }
}

// ---------------- exact fp32 dt_raw ----------------
__global__ void dtraw_kernel(const float* __restrict__ x, const float* __restrict__ W_in,
                             const float* __restrict__ b_in)
{
    int row0 = blockIdx.x * 8;
    int tid = threadIdx.x;
    int r = tid >> 5, h = tid & 31;
    __shared__ float xs[8][DMODEL];
    for (int i = tid; i < 8 * DMODEL; i += 256)
        xs[i >> 10][i & 1023] = x[(size_t)(row0 + (i >> 10)) * DMODEL + (i & 1023)];
    __syncthreads();
    const float* wc = W_in + (DINPROJ - NHEADS) + h;
    float a0 = 0.f, a1 = 0.f, a2 = 0.f, a3 = 0.f;
#pragma unroll 2
    for (int k = 0; k < DMODEL; k += 4) {
        a0 = fmaf(xs[r][k + 0], wc[(size_t)(k + 0) * DINPROJ], a0);
        a1 = fmaf(xs[r][k + 1], wc[(size_t)(k + 1) * DINPROJ], a1);
        a2 = fmaf(xs[r][k + 2], wc[(size_t)(k + 2) * DINPROJ], a2);
        a3 = fmaf(xs[r][k + 3], wc[(size_t)(k + 3) * DINPROJ], a3);
    }
    g_draw[(size_t)(row0 + r) * NHEADS + h] =
        b_in[DINPROJ - NHEADS + h] + ((a0 + a1) + (a2 + a3));
}

// ---------------- conv + silu + fused xdt (4 seq positions / thread) --------
__global__ void conv_kernel(const float* __restrict__ conv_w, const float* __restrict__ conv_b)
{
    int idx = blockIdx.x * blockDim.x + threadIdx.x;
    if (idx >= (NROWS / 4) * CONVDIM) return;
    int ch = idx % CONVDIM;
    int rg = idx / CONVDIM;
    int row0 = rg * 4;
    int l0 = row0 % SEQ;
    float w0 = conv_w[ch * DCONV + 0], w1 = conv_w[ch * DCONV + 1];
    float w2 = conv_w[ch * DCONV + 2], w3 = conv_w[ch * DCONV + 3];
    float bv = conv_b[ch];
    float v[7];
#pragma unroll
    for (int j = 0; j < 7; j++) {
        int l = l0 + j - 3;
        v[j] = (l >= 0) ? g_zx[(size_t)(row0 + j - 3) * DINPROJ + DINNER + ch] : 0.f;
    }
#pragma unroll
    for (int i = 0; i < 4; i++) {
        float a = bv;
        a = fmaf(v[i], w0, a);
        a = fmaf(v[i + 1], w1, a);
        a = fmaf(v[i + 2], w2, a);
        a = fmaf(v[i + 3], w3, a);
        float o = siluf(a);
        size_t row = row0 + i;
        g_xbc[row * CONVDIM + ch] = o;
        if (ch < DINNER)
            g_xdt[row * DINNER + ch] = o * g_dt[row * NHEADS + (ch >> 6)];
    }
}

// ---------------- dt / dA + per-chunk inclusive cumsum (exact exp) ----------
__global__ void dtscan_kernel(const float* __restrict__ tdiff,
                              const float* __restrict__ A_log,
                              const float* __restrict__ dt_bias,
                              const float* __restrict__ time_decay)
{
    int blk = blockIdx.x;
    int c = blk % NC;
    int h = (blk / NC) % NHEADS;
    int b = blk / (NC * NHEADS);
    int l = threadIdx.x;
    __shared__ float s[CHUNKL];
    int row = b * SEQ + c * CHUNKL + l;
    float draw = g_draw[(size_t)row * NHEADS + h];
    float dt = softplusf(draw + dt_bias[h]);
    float Ah = -expf(A_log[h]);
    float spd = softplusf(time_decay[h]);
    float dA = dt * Ah - spd * tdiff[row];
    g_dt[(size_t)row * NHEADS + h] = dt;
    s[l] = dA;
    __syncthreads();
    for (int off = 1; off < CHUNKL; off <<= 1) {
        float v = (l >= off) ? s[l - off] : 0.f;
        __syncthreads();
        s[l] += v;
        __syncthreads();
    }
    g_acum[((size_t)(b * NHEADS + h)) * SEQ + c * CHUNKL + l] = s[l];
}

// ---------------- G = C @ B^T per (b,chunk)  [tf32 mma, 64x64 tiles] --------
__global__ __launch_bounds__(256)
void cbgemm_kernel()
{
    int bc = blockIdx.z;
    int l0 = blockIdx.y * 64, s0 = blockIdx.x * 64;
    __shared__ float As[16][72];
    __shared__ float Bs2[16][72];
    int tid = threadIdx.x;
    int lane = tid & 31, wid = tid >> 5;
    int wm = (wid & 3) * 16;
    int wn = (wid >> 2) * 32;
    int g = lane >> 2, tig = lane & 3;

    float acc[4][4];
#pragma unroll
    for (int j = 0; j < 4; j++)
#pragma unroll
        for (int v = 0; v < 4; v++) acc[j][v] = 0.f;

    const float* base = g_xbc + (size_t)bc * CHUNKL * CONVDIM;
    int r = tid >> 2, c4 = (tid & 3) << 2;
    for (int n0 = 0; n0 < DSTATE; n0 += 16) {
        float4 vc = *(const float4*)(base + (size_t)(l0 + r) * CONVDIM + DINNER + DSTATE + n0 + c4);
        As[c4 + 0][r] = tf32r(vc.x); As[c4 + 1][r] = tf32r(vc.y);
        As[c4 + 2][r] = tf32r(vc.z); As[c4 + 3][r] = tf32r(vc.w);
        float4 vb = *(const float4*)(base + (size_t)(s0 + r) * CONVDIM + DINNER + n0 + c4);
        Bs2[c4 + 0][r] = tf32r(vb.x); Bs2[c4 + 1][r] = tf32r(vb.y);
        Bs2[c4 + 2][r] = tf32r(vb.z); Bs2[c4 + 3][r] = tf32r(vb.w);
        __syncthreads();
#pragma unroll
        for (int ks = 0; ks < 2; ks++) {
            int kb = ks * 8;
            unsigned af[4], bf[4][2];
            af[0] = __float_as_uint(As[kb + tig][wm + g]);
            af[1] = __float_as_uint(As[kb + tig][wm + g + 8]);
            af[2] = __float_as_uint(As[kb + tig + 4][wm + g]);
            af[3] = __float_as_uint(As[kb + tig + 4][wm + g + 8]);
#pragma unroll
            for (int nt = 0; nt < 4; nt++) {
                int n = wn + nt * 8;
                bf[nt][0] = __float_as_uint(Bs2[kb + tig][n + g]);
                bf[nt][1] = __float_as_uint(Bs2[kb + tig + 4][n + g]);
            }
#pragma unroll
            for (int nt = 0; nt < 4; nt++)
                mma_tf32(acc[nt], af, bf[nt]);
        }
        __syncthreads();
    }
    float* Gp = g_G + (size_t)bc * CHUNKL * CHUNKL;
    int rr = l0 + wm + g;
#pragma unroll
    for (int nt = 0; nt < 4; nt++) {
        int col = s0 + wn + nt * 8 + 2 * tig;
        Gp[(size_t)rr * CHUNKL + col]     = acc[nt][0];
        Gp[(size_t)rr * CHUNKL + col + 1] = acc[nt][1];
        Gp[(size_t)(rr + 8) * CHUNKL + col]     = acc[nt][2];
        Gp[(size_t)(rr + 8) * CHUNKL + col + 1] = acc[nt][3];
    }
}

// ---------------- chunk states  [tf32 mma, __expf] ----------------
__global__ __launch_bounds__(256)
void states_kernel()
{
    int bch = blockIdx.x;
    int h = bch % NHEADS;
    int bc = bch / NHEADS;
    int b = bc / NC, c = bc % NC;
    int tid = threadIdx.x;
    int lane = tid & 31, wid = tid >> 5;
    int wm = (wid >> 1) * 16;
    int wn = (wid & 1) * 64;
    int g = lane >> 2, tig = lane & 3;

    __shared__ float w[CHUNKL];
    __shared__ float As[16][72];
    __shared__ float Bs[16][136];
    const float* ac = g_acum + ((size_t)(b * NHEADS + h)) * SEQ + c * CHUNKL;
    w[tid] = __expf(ac[CHUNKL - 1] - ac[tid]);
    __syncthreads();

    float acc[8][4];
#pragma unroll
    for (int j = 0; j < 8; j++)
#pragma unroll
        for (int v = 0; v < 4; v++) acc[j][v] = 0.f;

    for (int l0 = 0; l0 < CHUNKL; l0 += 16) {
        {
            int lr = tid >> 4, pc = (tid & 15) << 2;
            float4 v = *(const float4*)(g_xdt + ((size_t)(bc * CHUNKL + l0 + lr)) * DINNER + h * HEADDIM + pc);
            float ww = w[l0 + lr];
            As[lr][pc + 0] = tf32r(v.x * ww); As[lr][pc + 1] = tf32r(v.y * ww);
            As[lr][pc + 2] = tf32r(v.z * ww); As[lr][pc + 3] = tf32r(v.w * ww);
        }
#pragma unroll
        for (int u = 0; u < 2; u++) {
            int id = tid * 2 + u;
            int lr2 = id >> 5, nc4 = (id & 31) << 2;
            float4 vb = *(const float4*)(g_xbc + ((size_t)(bc * CHUNKL + l0 + lr2)) * CONVDIM + DINNER + nc4);
            Bs[lr2][nc4 + 0] = tf32r(vb.x); Bs[lr2][nc4 + 1] = tf32r(vb.y);
            Bs[lr2][nc4 + 2] = tf32r(vb.z); Bs[lr2][nc4 + 3] = tf32r(vb.w);
        }
        __syncthreads();
#pragma unroll
        for (int ks = 0; ks < 2; ks++) {
            int kb = ks * 8;
            unsigned af[4], bf[8][2];
            af[0] = __float_as_uint(As[kb + tig][wm + g]);
            af[1] = __float_as_uint(As[kb + tig][wm + g + 8]);
            af[2] = __float_as_uint(As[kb + tig + 4][wm + g]);
            af[3] = __float_as_uint(As[kb + tig + 4][wm + g + 8]);
#pragma unroll
            for (int nt = 0; nt < 8; nt++) {
                int n = wn + nt * 8;
                bf[nt][0] = __float_as_uint(Bs[kb + tig][n + g]);
                bf[nt][1] = __float_as_uint(Bs[kb + tig + 4][n + g]);
            }
#pragma unroll
            for (int nt = 0; nt < 8; nt++)
                mma_tf32(acc[nt], af, bf[nt]);
        }
        __syncthreads();
    }
    float* sp = g_states + (size_t)bch * HEADDIM * DSTATE;
    int r = wm + g;
#pragma unroll
    for (int nt = 0; nt < 8; nt++) {
        int col = wn + nt * 8 + 2 * tig;
        sp[(size_t)r * DSTATE + col]     = acc[nt][0];
        sp[(size_t)r * DSTATE + col + 1] = acc[nt][1];
        sp[(size_t)(r + 8) * DSTATE + col]     = acc[nt][2];
        sp[(size_t)(r + 8) * DSTATE + col + 1] = acc[nt][3];
    }
}

// ---------------- inter-chunk scan  [__expf] ----------------
__global__ void scan_kernel()
{
    int idx = blockIdx.x * blockDim.x + threadIdx.x;
    if (idx >= BB * NHEADS * HEADDIM * DSTATE) return;
    int n = idx & 127;
    int p = (idx >> 7) & 63;
    int h = (idx >> 13) & 31;
    int b = idx >> 18;
    float carry = 0.f;
    for (int c = 0; c < NC; c++) {
        size_t off = ((size_t)((b * NC + c) * NHEADS + h)) * (HEADDIM * DSTATE) + p * DSTATE + n;
        g_prev[off] = carry;
        float cd = __expf(g_acum[((size_t)(b * NHEADS + h)) * SEQ + c * CHUNKL + CHUNKL - 1]);
        carry = carry * cd + g_states[off];
    }
}

// ---------------- Y = (Y_diag + Y_off + D*xh) * silu(z)  [tf32 mma, __expf] -
__global__ __launch_bounds__(256)
void ydiag_kernel(const float* __restrict__ Dp)
{
    int bch = blockIdx.x;
    int h = bch % NHEADS;
    int bc = bch / NHEADS;
    int b = bc / NC;
    int tid = threadIdx.x;
    int lane = tid & 31, wid = tid >> 5;
    int g = lane >> 2, tig = lane & 3;
    int wm = wid * 32;

    __shared__ float Acs[CHUNKL];
    __shared__ float Gs[16][260];
    __shared__ float Xs[16][68];

    const float* ac = g_acum + ((size_t)(b * NHEADS + h)) * SEQ + (bc % NC) * CHUNKL;
    Acs[tid] = ac[tid];
    __syncthreads();
    float al = Acs[tid];
    float eal = __expf(al);

    float acc[2][8][4];
#pragma unroll
    for (int i = 0; i < 2; i++)
#pragma unroll
        for (int j = 0; j < 8; j++)
#pragma unroll
            for (int v = 0; v < 4; v++) acc[i][j][v] = 0.f;

    const float* Gp = g_G + (size_t)bc * CHUNKL * CHUNKL;

    for (int s0 = 0; s0 < CHUNKL; s0 += 16) {
        float4 gv[4];
#pragma unroll
        for (int q = 0; q < 4; q++)
            gv[q] = *(const float4*)(Gp + (size_t)tid * CHUNKL + s0 + q * 4);
        const float* gf = (const float*)gv;
#pragma unroll
        for (int i = 0; i < 16; i++) {
            int s = s0 + i;
            float v = 0.f;
            if (tid >= s) v = gf[i] * __expf(al - Acs[s]);
            Gs[i][tid] = tf32r(v);
        }
        {
            int lr = tid >> 4, pc = (tid & 15) << 2;
            float4 v4 = *(const float4*)(g_xdt + ((size_t)(bc * CHUNKL + s0 + lr)) * DINNER + h * HEADDIM + pc);
            Xs[lr][pc + 0] = tf32r(v4.x); Xs[lr][pc + 1] = tf32r(v4.y);
            Xs[lr][pc + 2] = tf32r(v4.z); Xs[lr][pc + 3] = tf32r(v4.w);
        }
        __syncthreads();
#pragma unroll
        for (int ks = 0; ks < 2; ks++) {
            int kb = ks * 8;
            unsigned af[2][4], bf[8][2];
#pragma unroll
            for (int mt = 0; mt < 2; mt++) {
                int m = wm + mt * 16;
                af[mt][0] = __float_as_uint(Gs[kb + tig][m + g]);
                af[mt][1] = __float_as_uint(Gs[kb + tig][m + g + 8]);
                af[mt][2] = __float_as_uint(Gs[kb + tig + 4][m + g]);
                af[mt][3] = __float_as_uint(Gs[kb + tig + 4][m + g + 8]);
            }
#pragma unroll
            for (int nt = 0; nt < 8; nt++) {
                int n = nt * 8;
                bf[nt][0] = __float_as_uint(Xs[kb + tig][n + g]);
                bf[nt][1] = __float_as_uint(Xs[kb + tig + 4][n + g]);
            }
#pragma unroll
            for (int mt = 0; mt < 2; mt++)
#pragma unroll
                for (int nt = 0; nt < 8; nt++)
                    mma_tf32(acc[mt][nt], af[mt], bf[nt]);
        }
        __syncthreads();
    }

    const float* pv_base = g_prev + (size_t)bch * HEADDIM * DSTATE;
    for (int n0 = 0; n0 < DSTATE; n0 += 16) {
        float4 cv[4];
#pragma unroll
        for (int q = 0; q < 4; q++)
            cv[q] = *(const float4*)(g_xbc + ((size_t)(bc * CHUNKL + tid)) * CONVDIM + DINNER + DSTATE + n0 + q * 4);
        const float* cf = (const float*)cv;
#pragma unroll
        for (int i = 0; i < 16; i++)
            Gs[i][tid] = tf32r(cf[i] * eal);
        {
            int p = tid >> 2, k4 = (tid & 3) << 2;
            float4 pvv = *(const float4*)(pv_base + (size_t)p * DSTATE + n0 + k4);
            Xs[k4 + 0][p] = tf32r(pvv.x); Xs[k4 + 1][p] = tf32r(pvv.y);
            Xs[k4 + 2][p] = tf32r(pvv.z); Xs[k4 + 3][p] = tf32r(pvv.w);
        }
        __syncthreads();
#pragma unroll
        for (int ks = 0; ks < 2; ks++) {
            int kb = ks * 8;
            unsigned af[2][4], bf[8][2];
#pragma unroll
            for (int mt = 0; mt < 2; mt++) {
                int m = wm + mt * 16;
                af[mt][0] = __float_as_uint(Gs[kb + tig][m + g]);
                af[mt][1] = __float_as_uint(Gs[kb + tig][m + g + 8]);
                af[mt][2] = __float_as_uint(Gs[kb + tig + 4][m + g]);
                af[mt][3] = __float_as_uint(Gs[kb + tig + 4][m + g + 8]);
            }
#pragma unroll
            for (int nt = 0; nt < 8; nt++) {
                int n = nt * 8;
                bf[nt][0] = __float_as_uint(Xs[kb + tig][n + g]);
                bf[nt][1] = __float_as_uint(Xs[kb + tig + 4][n + g]);
            }
#pragma unroll
            for (int mt = 0; mt < 2; mt++)
#pragma unroll
                for (int nt = 0; nt < 8; nt++)
                    mma_tf32(acc[mt][nt], af[mt], bf[nt]);
        }
        __syncthreads();
    }

    float Dh = Dp[h];
#pragma unroll
    for (int mt = 0; mt < 2; mt++) {
        int r0 = wm + mt * 16 + g;
#pragma unroll
        for (int nt = 0; nt < 8; nt++) {
            int pcol = nt * 8 + 2 * tig;
            int d = h * HEADDIM + pcol;
#pragma unroll
            for (int half = 0; half < 2; half++) {
                int l = r0 + half * 8;
                size_t row = (size_t)bc * CHUNKL + l;
                float xh0 = g_xbc[row * CONVDIM + d];
                float xh1 = g_xbc[row * CONVDIM + d + 1];
                float z0 = g_zx[row * DINPROJ + d];
                float z1 = g_zx[row * DINPROJ + d + 1];
                float v0 = acc[mt][nt][half * 2 + 0] + Dh * xh0;
                float v1 = acc[mt][nt][half * 2 + 1] + Dh * xh1;
                v0 *= siluf(z0);
                v1 *= siluf(z1);
                g_y[row * DINNER + d] = v0;
                g_y[row * DINNER + d + 1] = v1;
            }
        }
    }
}

// ---------------- gated RMS norm (float4 + shuffle reduction) ----------------
__global__ void rms_kernel(const float* __restrict__ rms_w)
{
    int row = blockIdx.x;
    int tid = threadIdx.x;
    float4* y4 = (float4*)(g_y + (size_t)row * DINNER);
    const float4* w4 = (const float4*)rms_w;
    __shared__ float red8[8];
    float4 v0 = y4[tid], v1 = y4[tid + 256];
    float ss = v0.x * v0.x + v0.y * v0.y + v0.z * v0.z + v0.w * v0.w
             + v1.x * v1.x + v1.y * v1.y + v1.z * v1.z + v1.w * v1.w;
    float tot = block_sum256(ss, red8, tid);
    __shared__ float sc;
    if (tid == 0) sc = rsqrtf(tot * (1.f / DINNER) + 1e-12f);
    __syncthreads();
    float scale = sc;
    float4 g0 = w4[tid], g1 = w4[tid + 256];
    v0.x *= scale * g0.x; v0.y *= scale * g0.y; v0.z *= scale * g0.z; v0.w *= scale * g0.w;
    v1.x *= scale * g1.x; v1.y *= scale * g1.y; v1.z *= scale * g1.z; v1.w *= scale * g1.w;
    y4[tid] = v0; y4[tid + 256] = v1;
}

// ---------------- residual add + LayerNorm (float4 + shuffle reduction) ------
__global__ void addln_kernel(const float* __restrict__ in1, const float* __restrict__ res,
                             const float* __restrict__ g, const float* __restrict__ bta,
                             float* __restrict__ out)
{
    int row = blockIdx.x;
    int tid = threadIdx.x;
    __shared__ float red8[8];
    __shared__ float s_mu, s_inv;
    float4 a = ((const float4*)(in1 + (size_t)row * DMODEL))[tid];
    float4 b = ((const float4*)(res + (size_t)row * DMODEL))[tid];
    float4 v;
    v.x = a.x + b.x; v.y = a.y + b.y; v.z = a.z + b.z; v.w = a.w + b.w;
    float s = (v.x + v.y) + (v.z + v.w);
    float tot = block_sum256(s, red8, tid);
    if (tid == 0) s_mu = tot * (1.f / DMODEL);
    __syncthreads();
    float mu = s_mu;
    float dx = v.x - mu, dy = v.y - mu, dz = v.z - mu, dw = v.w - mu;
    float vs = dx * dx + dy * dy + dz * dz + dw * dw;
    float vtot = block_sum256(vs, red8, tid);
    if (tid == 0) s_inv = rsqrtf(vtot * (1.f / DMODEL) + 1e-12f);
    __syncthreads();
    float inv = s_inv;
    float4 gg = ((const float4*)g)[tid];
    float4 bb = ((const float4*)bta)[tid];
    float4 o;
    o.x = dx * inv * gg.x + bb.x;
    o.y = dy * inv * gg.y + bb.y;
    o.z = dz * inv * gg.z + bb.z;
    o.w = dw * inv * gg.w + bb.w;
    ((float4*)(out + (size_t)row * DMODEL))[tid] = o;
}

// ---------------- launch ----------------
extern "C" void kernel_launch(void* const* d_in, const int* in_sizes, int n_in,
                              void* d_out, int out_size)
{
    const float* x          = (const float*)d_in[0];
    const float* time_diff  = (const float*)d_in[1];
    const float* W_in       = (const float*)d_in[2];
    const float* b_in       = (const float*)d_in[3];
    const float* conv_w     = (const float*)d_in[4];
    const float* conv_b     = (const float*)d_in[5];
    const float* A_log      = (const float*)d_in[6];
    const float* dt_bias    = (const float*)d_in[7];
    const float* Dp         = (const float*)d_in[8];
    const float* time_decay = (const float*)d_in[9];
    const float* rms_w      = (const float*)d_in[10];
    const float* W_out      = (const float*)d_in[11];
    const float* b_out      = (const float*)d_in[12];
    const float* ln_g       = (const float*)d_in[13];
    const float* ln_b       = (const float*)d_in[14];
    const float* fc1_w      = (const float*)d_in[15];
    const float* fc1_b      = (const float*)d_in[16];
    const float* fc2_w      = (const float*)d_in[17];
    const float* fc2_b      = (const float*)d_in[18];
    const float* ln2_g      = (const float*)d_in[19];
    const float* ln2_b      = (const float*)d_in[20];
    float* out = (float*)d_out;

    float *p_zx, *p_y, *p_hidden, *p_h, *p_ff, *p_ff2;
    cudaGetSymbolAddress((void**)&p_zx, g_zx);
    cudaGetSymbolAddress((void**)&p_y, g_y);
    cudaGetSymbolAddress((void**)&p_hidden, g_hidden);
    cudaGetSymbolAddress((void**)&p_h, g_h);
    cudaGetSymbolAddress((void**)&p_ff, g_ff);
    cudaGetSymbolAddress((void**)&p_ff2, g_ff2);

    cudaFuncSetAttribute(gemm_tc, cudaFuncAttributeMaxDynamicSharedMemorySize, GT_SMEM);

    // 1. in_proj
    gemm_tc<<<dim3((DINPROJ + 127) / 128, NROWS / 128), 256, GT_SMEM>>>(
        x, W_in, b_in, p_zx, NROWS, DINPROJ, DMODEL, 0);
    // 1b. exact fp32 dt_raw
    dtraw_kernel<<<NROWS / 8, 256>>>(x, W_in, b_in);
    // 2. dt / dA / chunk cumsum
    dtscan_kernel<<<BB * NHEADS * NC, CHUNKL>>>(time_diff, A_log, dt_bias, time_decay);
    // 3. conv + silu + fused xdt
    conv_kernel<<<((NROWS / 4) * CONVDIM + 255) / 256, 256>>>(conv_w, conv_b);
    // 4. G = C @ B^T  [tf32, 64x64]
    cbgemm_kernel<<<dim3(4, 4, BB * NC), 256>>>();
    // 5. chunk states [tf32, __expf]
    states_kernel<<<BB * NC * NHEADS, 256>>>();
    // 6. inter-chunk scan [__expf]
    scan_kernel<<<(BB * NHEADS * HEADDIM * DSTATE + 255) / 256, 256>>>();
    // 7. Y [tf32, __expf]
    ydiag_kernel<<<BB * NC * NHEADS, 256>>>(Dp);
    // 8. gated RMS norm (vectorized)
    rms_kernel<<<NROWS, 256>>>(rms_w);
    // 9. out_proj
    gemm_tc<<<dim3(DMODEL / 128, NROWS / 128), 256, GT_SMEM>>>(
        p_y, W_out, b_out, p_hidden, NROWS, DMODEL, DINNER, 0);
    // 10. h = LN(hidden + x)  (vectorized)
    addln_kernel<<<NROWS, 256>>>(p_hidden, x, ln_g, ln_b, p_h);
    // 11. fc1 + hardswish
    gemm_tc<<<dim3(DFF / 128, NROWS / 128), 256, GT_SMEM>>>(
        p_h, fc1_w, fc1_b, p_ff, NROWS, DFF, DMODEL, 1);
    // 12. fc2
    gemm_tc<<<dim3(DMODEL / 128, NROWS / 128), 256, GT_SMEM>>>(
        p_ff, fc2_w, fc2_b, p_ff2, NROWS, DMODEL, DFF, 0);
    // 13. out = LN(ff2 + h)  (vectorized)
    addln_kernel<<<NROWS, 256>>>(p_ff2, p_h, ln2_g, ln2_b, out);
    // 14. time_diff passthrough
    cudaMemcpyAsync(out + (size_t)NROWS * DMODEL, time_diff,
                    (size_t)BB * SEQ * sizeof(float), cudaMemcpyDeviceToDevice);
}

// round 16
// speedup vs baseline: 1.4780x; 1.0025x over previous
#include <cuda_runtime.h>
#include <math.h>

// ---------------- problem constants ----------------
#define BB       2
#define SEQ      2048
#define DMODEL   1024
#define DCONV    4
#define HEADDIM  64
#define CHUNKL   256
#define DINNER   2048
#define NHEADS   32
#define CONVDIM  2304   // DINNER + 2*DSTATE
#define DINPROJ  4384   // 2*DINNER + 2*DSTATE + NHEADS
#define DSTATE   128
#define DFF      4096
#define NC       8      // SEQ / CHUNKL
#define NROWS    (BB*SEQ)   // 4096

// ---------------- scratch (device globals; no runtime alloc) ----------------
__device__ float g_zx[(size_t)NROWS*DINPROJ];
__device__ float g_xbc[(size_t)NROWS*CONVDIM];
__device__ float g_xdt[(size_t)NROWS*DINNER];
__device__ float g_dt[(size_t)NROWS*NHEADS];
__device__ float g_draw[(size_t)NROWS*NHEADS];
__device__ float g_acum[(size_t)BB*NHEADS*SEQ];
__device__ float g_G[(size_t)BB*NC*CHUNKL*CHUNKL];
__device__ float g_states[(size_t)BB*NC*NHEADS*HEADDIM*DSTATE];
__device__ float g_prev  [(size_t)BB*NC*NHEADS*HEADDIM*DSTATE];
__device__ float g_y[(size_t)NROWS*DINNER];
__device__ float g_hidden[(size_t)NROWS*DMODEL];
__device__ float g_h[(size_t)NROWS*DMODEL];
__device__ float g_ff[(size_t)NROWS*DFF];
__device__ float g_ff2[(size_t)NROWS*DMODEL];

// ---------------- helpers ----------------
__device__ __forceinline__ float softplusf(float x) {
    return (x > 20.f) ? x : log1pf(expf(x));
}
__device__ __forceinline__ float siluf(float x) {
    return x / (1.f + expf(-x));
}
__device__ __forceinline__ float tf32r(float x) {
    unsigned r;
    asm("cvt.rna.tf32.f32 %0, %1;" : "=r"(r) : "f"(x));
    return __uint_as_float(r);
}
__device__ __forceinline__ unsigned tf32u(float x) {
    unsigned r;
    asm("cvt.rna.tf32.f32 %0, %1;" : "=r"(r) : "f"(x));
    return r;
}
__device__ __forceinline__ unsigned smem_u32(const void* p) {
    unsigned a;
    asm("{ .reg .u64 t; cvta.to.shared.u64 t, %1; cvt.u32.u64 %0, t; }" : "=r"(a) : "l"(p));
    return a;
}
__device__ __forceinline__ void mma_tf32(float* c, const unsigned* a, const unsigned* b) {
    asm volatile("mma.sync.aligned.m16n8k8.row.col.f32.tf32.tf32.f32 "
                 "{%0,%1,%2,%3}, {%4,%5,%6,%7}, {%8,%9}, {%0,%1,%2,%3};"
                 : "+f"(c[0]), "+f"(c[1]), "+f"(c[2]), "+f"(c[3])
                 : "r"(a[0]), "r"(a[1]), "r"(a[2]), "r"(a[3]),
                   "r"(b[0]), "r"(b[1]));
}
// block reduction over 256 threads (8 warps) via shuffles, 1 barrier
__device__ __forceinline__ float block_sum256(float v, float* red8, int tid) {
#pragma unroll
    for (int o = 16; o > 0; o >>= 1)
        v += __shfl_down_sync(0xffffffffu, v, o);
    if ((tid & 31) == 0) red8[tid >> 5] = v;
    __syncthreads();
    float s = (tid < 8) ? red8[tid] : 0.f;
#pragma unroll
    for (int o = 4; o > 0; o >>= 1)
        s += __shfl_down_sync(0xffu, s, o);
    return __shfl_sync(0xffffffffu, s, 0, 32);   // valid in warp 0
}

// ---------------- cp.async pipelined TF32 GEMM: C = act(A@B+bias) -----------
// CTA tile 128x128, warp tile 32x64, 3-stage pipeline, 2 CTAs/SM.  (R10 champion)
#define GSTAGES 3
#define ASTR    20                       // A smem stride (floats): conflict-free
#define BSTR    136                      // B smem stride (floats)
#define A_STF   (128*ASTR)               // 2560 floats per A stage
#define B_STF   (16*BSTR)                // 2176 floats per B stage
#define ST_F    (A_STF + B_STF)          // 4736
#define GT_SMEM (GSTAGES*ST_F*4)         // 56832 bytes

#define GT_ISSUE(stg, kt) do {                                                      \
    unsigned sb = smb + (unsigned)(stg) * (ST_F * 4);                               \
    unsigned bbs = sb + A_STF * 4;                                                  \
    int k0i = (kt) * 16;                                                            \
    _Pragma("unroll")                                                               \
    for (int u = 0; u < 2; u++) {                                                   \
        int c = tid * 2 + u;                                                        \
        int m = c >> 2, kq = (c & 3) << 2;                                          \
        const float* sp = A + (size_t)(row0 + m) * K + k0i + kq;                    \
        asm volatile("cp.async.cg.shared.global [%0], [%1], 16;"                    \
                     :: "r"(sb + (unsigned)(m * ASTR + kq) * 4), "l"(sp));          \
        int kk = c >> 5, nq = (c & 31) << 2;                                        \
        int gc = col0 + nq;                                                         \
        const float* sp2 = (gc < N) ? (B + (size_t)(k0i + kk) * N + gc) : B;        \
        int by = (gc < N) ? 16 : 0;                                                 \
        asm volatile("cp.async.cg.shared.global [%0], [%1], 16, %2;"                \
                     :: "r"(bbs + (unsigned)(kk * BSTR + nq) * 4), "l"(sp2), "r"(by)); \
    }                                                                               \
    asm volatile("cp.async.commit_group;" ::: "memory");                            \
} while (0)

__global__ __launch_bounds__(256, 2)
void gemm_tc(const float* __restrict__ A, const float* __restrict__ B,
             const float* __restrict__ bias, float* __restrict__ C,
             int M, int N, int K, int act)
{
    extern __shared__ float sm[];
    unsigned smb = smem_u32(sm);
    int tid = threadIdx.x;
    int lane = tid & 31, wid = tid >> 5;
    int wm = (wid >> 1) * 32;
    int wn = (wid & 1) * 64;
    int g = lane >> 2, tig = lane & 3;
    int row0 = blockIdx.y * 128, col0 = blockIdx.x * 128;

    float acc[2][8][4];
#pragma unroll
    for (int i = 0; i < 2; i++)
#pragma unroll
        for (int j = 0; j < 8; j++)
#pragma unroll
            for (int v = 0; v < 4; v++) acc[i][j][v] = 0.f;

    int nt = K / 16;           // >= 64 for all call sites
    GT_ISSUE(0, 0);
    GT_ISSUE(1, 1);

    int stg = 0;               // buffer holding tile t
    for (int t = 0; t < nt; t++) {
        if (t + 2 <= nt) asm volatile("cp.async.wait_group 1;" ::: "memory");
        else             asm volatile("cp.async.wait_group 0;" ::: "memory");
        __syncthreads();
        if (t + 2 < nt) {
            int nstg = stg + 2; if (nstg >= GSTAGES) nstg -= GSTAGES;
            GT_ISSUE(nstg, t + 2);
        }

        const float* Ab = sm + stg * ST_F;
        const float* Bb = Ab + A_STF;
#pragma unroll
        for (int ks = 0; ks < 2; ks++) {
            int kb = ks * 8;
            unsigned af[2][4], bf[8][2];
#pragma unroll
            for (int mt = 0; mt < 2; mt++) {
                int m = wm + mt * 16;
                af[mt][0] = tf32u(Ab[(m + g) * ASTR + kb + tig]);
                af[mt][1] = tf32u(Ab[(m + g + 8) * ASTR + kb + tig]);
                af[mt][2] = tf32u(Ab[(m + g) * ASTR + kb + tig + 4]);
                af[mt][3] = tf32u(Ab[(m + g + 8) * ASTR + kb + tig + 4]);
            }
#pragma unroll
            for (int nt2 = 0; nt2 < 8; nt2++) {
                int n = wn + nt2 * 8;
                bf[nt2][0] = tf32u(Bb[(kb + tig) * BSTR + n + g]);
                bf[nt2][1] = tf32u(Bb[(kb + tig + 4) * BSTR + n + g]);
            }
#pragma unroll
            for (int mt = 0; mt < 2; mt++)
#pragma unroll
                for (int nt2 = 0; nt2 < 8; nt2++)
                    mma_tf32(acc[mt][nt2], af[mt], bf[nt2]);
        }
        stg++; if (stg >= GSTAGES) stg = 0;
    }

    // epilogue
#pragma unroll
    for (int mt = 0; mt < 2; mt++) {
        int r = row0 + wm + mt * 16 + g;
#pragma unroll
        for (int nt2 = 0; nt2 < 8; nt2++) {
            int col = col0 + wn + nt2 * 8 + 2 * tig;
            if (col < N) {
                float b0 = bias[col], b1 = bias[col + 1];
                float v0 = acc[mt][nt2][0] + b0;
                float v1 = acc[mt][nt2][1] + b1;
                float v2 = acc[mt][nt2][2] + b0;
                float v3 = acc[mt][nt2][3] + b1;
                if (act == 1) {
                    float t;
                    t = fminf(fmaxf(v0 + 3.f, 0.f), 6.f); v0 = v0 * t * (1.f / 6.f);
                    t = fminf(fmaxf(v1 + 3.f, 0.f), 6.f); v1 = v1 * t * (1.f / 6.f);
                    t = fminf(fmaxf(v2 + 3.f, 0.f), 6.f); v2 = v2 * t * (1.f / 6.f);
                    t = fminf(fmaxf(v3 + 3.f, 0.f), 6.f); v3 = v3 * t * (1.f / 6.f);
                }
                C[(size_t)r * N + col] = v0;
                C[(size_t)r * N + col + 1] = v1;
                C[(size_t)(r + 8) * N + col] = v2;
                C[(size_t)(r + 8) * N + col + 1] = v3;
            }
        }
    }
}

// ---------------- exact fp32 dt_raw ----------------
__global__ void dtraw_kernel(const float* __restrict__ x, const float* __restrict__ W_in,
                             const float* __restrict__ b_in)
{
    int row0 = blockIdx.x * 8;
    int tid = threadIdx.x;
    int r = tid >> 5, h = tid & 31;
    __shared__ float xs[8][DMODEL];
    for (int i = tid; i < 8 * DMODEL; i += 256)
        xs[i >> 10][i & 1023] = x[(size_t)(row0 + (i >> 10)) * DMODEL + (i & 1023)];
    __syncthreads();
    const float* wc = W_in + (DINPROJ - NHEADS) + h;
    float a0 = 0.f, a1 = 0.f, a2 = 0.f, a3 = 0.f;
#pragma unroll 2
    for (int k = 0; k < DMODEL; k += 4) {
        a0 = fmaf(xs[r][k + 0], wc[(size_t)(k + 0) * DINPROJ], a0);
        a1 = fmaf(xs[r][k + 1], wc[(size_t)(k + 1) * DINPROJ], a1);
        a2 = fmaf(xs[r][k + 2], wc[(size_t)(k + 2) * DINPROJ], a2);
        a3 = fmaf(xs[r][k + 3], wc[(size_t)(k + 3) * DINPROJ], a3);
    }
    g_draw[(size_t)(row0 + r) * NHEADS + h] =
        b_in[DINPROJ - NHEADS + h] + ((a0 + a1) + (a2 + a3));
}

// ---------------- conv + silu + fused xdt (4 rows x 4 channels / thread) ----
__global__ void conv_kernel(const float* __restrict__ conv_w, const float* __restrict__ conv_b)
{
    int idx = blockIdx.x * blockDim.x + threadIdx.x;
    if (idx >= (NROWS / 4) * (CONVDIM / 4)) return;
    int ch4 = (idx % (CONVDIM / 4)) * 4;
    int rg = idx / (CONVDIM / 4);
    int row0 = rg * 4;
    int l0 = row0 % SEQ;

    // weights: 4 channels x 4 taps (conv_w row-major [ch][tap])
    float4 w0 = *(const float4*)(conv_w + (ch4 + 0) * DCONV);
    float4 w1 = *(const float4*)(conv_w + (ch4 + 1) * DCONV);
    float4 w2 = *(const float4*)(conv_w + (ch4 + 2) * DCONV);
    float4 w3 = *(const float4*)(conv_w + (ch4 + 3) * DCONV);
    float4 bv = *(const float4*)(conv_b + ch4);

    float4 v[7];
#pragma unroll
    for (int j = 0; j < 7; j++) {
        int l = l0 + j - 3;
        if (l >= 0)
            v[j] = *(const float4*)(g_zx + (size_t)(row0 + j - 3) * DINPROJ + DINNER + ch4);
        else
            v[j] = make_float4(0.f, 0.f, 0.f, 0.f);
    }

    int head = ch4 >> 6;
    bool isx = ch4 < DINNER;
#pragma unroll
    for (int i = 0; i < 4; i++) {
        float4 a;
        a.x = bv.x + v[i].x * w0.x + v[i + 1].x * w0.y + v[i + 2].x * w0.z + v[i + 3].x * w0.w;
        a.y = bv.y + v[i].y * w1.x + v[i + 1].y * w1.y + v[i + 2].y * w1.z + v[i + 3].y * w1.w;
        a.z = bv.z + v[i].z * w2.x + v[i + 1].z * w2.y + v[i + 2].z * w2.z + v[i + 3].z * w2.w;
        a.w = bv.w + v[i].w * w3.x + v[i + 1].w * w3.y + v[i + 2].w * w3.z + v[i + 3].w * w3.w;
        float4 o;
        o.x = siluf(a.x); o.y = siluf(a.y); o.z = siluf(a.z); o.w = siluf(a.w);
        size_t row = row0 + i;
        *(float4*)(g_xbc + row * CONVDIM + ch4) = o;
        if (isx) {
            float dt = g_dt[row * NHEADS + head];
            float4 xo;
            xo.x = o.x * dt; xo.y = o.y * dt; xo.z = o.z * dt; xo.w = o.w * dt;
            *(float4*)(g_xdt + row * DINNER + ch4) = xo;
        }
    }
}

// ---------------- dt / dA + per-chunk inclusive cumsum (shuffle scan) -------
__global__ void dtscan_kernel(const float* __restrict__ tdiff,
                              const float* __restrict__ A_log,
                              const float* __restrict__ dt_bias,
                              const float* __restrict__ time_decay)
{
    int blk = blockIdx.x;
    int c = blk % NC;
    int h = (blk / NC) % NHEADS;
    int b = blk / (NC * NHEADS);
    int l = threadIdx.x;
    int lane = l & 31, wid = l >> 5;
    __shared__ float wsum[8];
    int row = b * SEQ + c * CHUNKL + l;
    float draw = g_draw[(size_t)row * NHEADS + h];
    float dt = softplusf(draw + dt_bias[h]);
    float Ah = -expf(A_log[h]);
    float spd = softplusf(time_decay[h]);
    float val = dt * Ah - spd * tdiff[row];
    g_dt[(size_t)row * NHEADS + h] = dt;
    // intra-warp inclusive scan
#pragma unroll
    for (int o = 1; o < 32; o <<= 1) {
        float n = __shfl_up_sync(0xffffffffu, val, o);
        if (lane >= o) val += n;
    }
    if (lane == 31) wsum[wid] = val;
    __syncthreads();
    // warp 0 scans the 8 warp totals (exclusive)
    if (wid == 0 && lane < 8) {
        float w = wsum[lane];
#pragma unroll
        for (int o = 1; o < 8; o <<= 1) {
            float n = __shfl_up_sync(0xffu, w, o);
            if (lane >= o) w += n;
        }
        wsum[lane] = w;   // inclusive warp-prefix
    }
    __syncthreads();
    if (wid > 0) val += wsum[wid - 1];
    g_acum[((size_t)(b * NHEADS + h)) * SEQ + c * CHUNKL + l] = val;
}

// ---------------- G = C @ B^T per (b,chunk)  [tf32 mma, 64x64 tiles] --------
__global__ __launch_bounds__(256)
void cbgemm_kernel()
{
    int bc = blockIdx.z;
    int l0 = blockIdx.y * 64, s0 = blockIdx.x * 64;
    __shared__ float As[16][72];
    __shared__ float Bs2[16][72];
    int tid = threadIdx.x;
    int lane = tid & 31, wid = tid >> 5;
    int wm = (wid & 3) * 16;
    int wn = (wid >> 2) * 32;
    int g = lane >> 2, tig = lane & 3;

    float acc[4][4];
#pragma unroll
    for (int j = 0; j < 4; j++)
#pragma unroll
        for (int v = 0; v < 4; v++) acc[j][v] = 0.f;

    const float* base = g_xbc + (size_t)bc * CHUNKL * CONVDIM;
    int r = tid >> 2, c4 = (tid & 3) << 2;
    for (int n0 = 0; n0 < DSTATE; n0 += 16) {
        float4 vc = *(const float4*)(base + (size_t)(l0 + r) * CONVDIM + DINNER + DSTATE + n0 + c4);
        As[c4 + 0][r] = tf32r(vc.x); As[c4 + 1][r] = tf32r(vc.y);
        As[c4 + 2][r] = tf32r(vc.z); As[c4 + 3][r] = tf32r(vc.w);
        float4 vb = *(const float4*)(base + (size_t)(s0 + r) * CONVDIM + DINNER + n0 + c4);
        Bs2[c4 + 0][r] = tf32r(vb.x); Bs2[c4 + 1][r] = tf32r(vb.y);
        Bs2[c4 + 2][r] = tf32r(vb.z); Bs2[c4 + 3][r] = tf32r(vb.w);
        __syncthreads();
#pragma unroll
        for (int ks = 0; ks < 2; ks++) {
            int kb = ks * 8;
            unsigned af[4], bf[4][2];
            af[0] = __float_as_uint(As[kb + tig][wm + g]);
            af[1] = __float_as_uint(As[kb + tig][wm + g + 8]);
            af[2] = __float_as_uint(As[kb + tig + 4][wm + g]);
            af[3] = __float_as_uint(As[kb + tig + 4][wm + g + 8]);
#pragma unroll
            for (int nt = 0; nt < 4; nt++) {
                int n = wn + nt * 8;
                bf[nt][0] = __float_as_uint(Bs2[kb + tig][n + g]);
                bf[nt][1] = __float_as_uint(Bs2[kb + tig + 4][n + g]);
            }
#pragma unroll
            for (int nt = 0; nt < 4; nt++)
                mma_tf32(acc[nt], af, bf[nt]);
        }
        __syncthreads();
    }
    float* Gp = g_G + (size_t)bc * CHUNKL * CHUNKL;
    int rr = l0 + wm + g;
#pragma unroll
    for (int nt = 0; nt < 4; nt++) {
        int col = s0 + wn + nt * 8 + 2 * tig;
        Gp[(size_t)rr * CHUNKL + col]     = acc[nt][0];
        Gp[(size_t)rr * CHUNKL + col + 1] = acc[nt][1];
        Gp[(size_t)(rr + 8) * CHUNKL + col]     = acc[nt][2];
        Gp[(size_t)(rr + 8) * CHUNKL + col + 1] = acc[nt][3];
    }
}

// ---------------- chunk states  [tf32 mma, __expf] ----------------
__global__ __launch_bounds__(256)
void states_kernel()
{
    int bch = blockIdx.x;
    int h = bch % NHEADS;
    int bc = bch / NHEADS;
    int b = bc / NC, c = bc % NC;
    int tid = threadIdx.x;
    int lane = tid & 31, wid = tid >> 5;
    int wm = (wid >> 1) * 16;
    int wn = (wid & 1) * 64;
    int g = lane >> 2, tig = lane & 3;

    __shared__ float w[CHUNKL];
    __shared__ float As[16][72];
    __shared__ float Bs[16][136];
    const float* ac = g_acum + ((size_t)(b * NHEADS + h)) * SEQ + c * CHUNKL;
    w[tid] = __expf(ac[CHUNKL - 1] - ac[tid]);
    __syncthreads();

    float acc[8][4];
#pragma unroll
    for (int j = 0; j < 8; j++)
#pragma unroll
        for (int v = 0; v < 4; v++) acc[j][v] = 0.f;

    for (int l0 = 0; l0 < CHUNKL; l0 += 16) {
        {
            int lr = tid >> 4, pc = (tid & 15) << 2;
            float4 v = *(const float4*)(g_xdt + ((size_t)(bc * CHUNKL + l0 + lr)) * DINNER + h * HEADDIM + pc);
            float ww = w[l0 + lr];
            As[lr][pc + 0] = tf32r(v.x * ww); As[lr][pc + 1] = tf32r(v.y * ww);
            As[lr][pc + 2] = tf32r(v.z * ww); As[lr][pc + 3] = tf32r(v.w * ww);
        }
#pragma unroll
        for (int u = 0; u < 2; u++) {
            int id = tid * 2 + u;
            int lr2 = id >> 5, nc4 = (id & 31) << 2;
            float4 vb = *(const float4*)(g_xbc + ((size_t)(bc * CHUNKL + l0 + lr2)) * CONVDIM + DINNER + nc4);
            Bs[lr2][nc4 + 0] = tf32r(vb.x); Bs[lr2][nc4 + 1] = tf32r(vb.y);
            Bs[lr2][nc4 + 2] = tf32r(vb.z); Bs[lr2][nc4 + 3] = tf32r(vb.w);
        }
        __syncthreads();
#pragma unroll
        for (int ks = 0; ks < 2; ks++) {
            int kb = ks * 8;
            unsigned af[4], bf[8][2];
            af[0] = __float_as_uint(As[kb + tig][wm + g]);
            af[1] = __float_as_uint(As[kb + tig][wm + g + 8]);
            af[2] = __float_as_uint(As[kb + tig + 4][wm + g]);
            af[3] = __float_as_uint(As[kb + tig + 4][wm + g + 8]);
#pragma unroll
            for (int nt = 0; nt < 8; nt++) {
                int n = wn + nt * 8;
                bf[nt][0] = __float_as_uint(Bs[kb + tig][n + g]);
                bf[nt][1] = __float_as_uint(Bs[kb + tig + 4][n + g]);
            }
#pragma unroll
            for (int nt = 0; nt < 8; nt++)
                mma_tf32(acc[nt], af, bf[nt]);
        }
        __syncthreads();
    }
    float* sp = g_states + (size_t)bch * HEADDIM * DSTATE;
    int r = wm + g;
#pragma unroll
    for (int nt = 0; nt < 8; nt++) {
        int col = wn + nt * 8 + 2 * tig;
        sp[(size_t)r * DSTATE + col]     = acc[nt][0];
        sp[(size_t)r * DSTATE + col + 1] = acc[nt][1];
        sp[(size_t)(r + 8) * DSTATE + col]     = acc[nt][2];
        sp[(size_t)(r + 8) * DSTATE + col + 1] = acc[nt][3];
    }
}

// ---------------- inter-chunk scan  [__expf] ----------------
__global__ void scan_kernel()
{
    int idx = blockIdx.x * blockDim.x + threadIdx.x;
    if (idx >= BB * NHEADS * HEADDIM * DSTATE) return;
    int n = idx & 127;
    int p = (idx >> 7) & 63;
    int h = (idx >> 13) & 31;
    int b = idx >> 18;
    float carry = 0.f;
    for (int c = 0; c < NC; c++) {
        size_t off = ((size_t)((b * NC + c) * NHEADS + h)) * (HEADDIM * DSTATE) + p * DSTATE + n;
        g_prev[off] = carry;
        float cd = __expf(g_acum[((size_t)(b * NHEADS + h)) * SEQ + c * CHUNKL + CHUNKL - 1]);
        carry = carry * cd + g_states[off];
    }
}

// ---------------- Y = (Y_diag + Y_off + D*xh) * silu(z)  [tf32 mma, __expf] -
__global__ __launch_bounds__(256)
void ydiag_kernel(const float* __restrict__ Dp)
{
    int bch = blockIdx.x;
    int h = bch % NHEADS;
    int bc = bch / NHEADS;
    int b = bc / NC;
    int tid = threadIdx.x;
    int lane = tid & 31, wid = tid >> 5;
    int g = lane >> 2, tig = lane & 3;
    int wm = wid * 32;

    __shared__ float Acs[CHUNKL];
    __shared__ float Gs[16][260];
    __shared__ float Xs[16][68];

    const float* ac = g_acum + ((size_t)(b * NHEADS + h)) * SEQ + (bc % NC) * CHUNKL;
    Acs[tid] = ac[tid];
    __syncthreads();
    float al = Acs[tid];
    float eal = __expf(al);

    float acc[2][8][4];
#pragma unroll
    for (int i = 0; i < 2; i++)
#pragma unroll
        for (int j = 0; j < 8; j++)
#pragma unroll
            for (int v = 0; v < 4; v++) acc[i][j][v] = 0.f;

    const float* Gp = g_G + (size_t)bc * CHUNKL * CHUNKL;

    for (int s0 = 0; s0 < CHUNKL; s0 += 16) {
        float4 gv[4];
#pragma unroll
        for (int q = 0; q < 4; q++)
            gv[q] = *(const float4*)(Gp + (size_t)tid * CHUNKL + s0 + q * 4);
        const float* gf = (const float*)gv;
#pragma unroll
        for (int i = 0; i < 16; i++) {
            int s = s0 + i;
            float v = 0.f;
            if (tid >= s) v = gf[i] * __expf(al - Acs[s]);
            Gs[i][tid] = tf32r(v);
        }
        {
            int lr = tid >> 4, pc = (tid & 15) << 2;
            float4 v4 = *(const float4*)(g_xdt + ((size_t)(bc * CHUNKL + s0 + lr)) * DINNER + h * HEADDIM + pc);
            Xs[lr][pc + 0] = tf32r(v4.x); Xs[lr][pc + 1] = tf32r(v4.y);
            Xs[lr][pc + 2] = tf32r(v4.z); Xs[lr][pc + 3] = tf32r(v4.w);
        }
        __syncthreads();
#pragma unroll
        for (int ks = 0; ks < 2; ks++) {
            int kb = ks * 8;
            unsigned af[2][4], bf[8][2];
#pragma unroll
            for (int mt = 0; mt < 2; mt++) {
                int m = wm + mt * 16;
                af[mt][0] = __float_as_uint(Gs[kb + tig][m + g]);
                af[mt][1] = __float_as_uint(Gs[kb + tig][m + g + 8]);
                af[mt][2] = __float_as_uint(Gs[kb + tig + 4][m + g]);
                af[mt][3] = __float_as_uint(Gs[kb + tig + 4][m + g + 8]);
            }
#pragma unroll
            for (int nt = 0; nt < 8; nt++) {
                int n = nt * 8;
                bf[nt][0] = __float_as_uint(Xs[kb + tig][n + g]);
                bf[nt][1] = __float_as_uint(Xs[kb + tig + 4][n + g]);
            }
#pragma unroll
            for (int mt = 0; mt < 2; mt++)
#pragma unroll
                for (int nt = 0; nt < 8; nt++)
                    mma_tf32(acc[mt][nt], af[mt], bf[nt]);
        }
        __syncthreads();
    }

    const float* pv_base = g_prev + (size_t)bch * HEADDIM * DSTATE;
    for (int n0 = 0; n0 < DSTATE; n0 += 16) {
        float4 cv[4];
#pragma unroll
        for (int q = 0; q < 4; q++)
            cv[q] = *(const float4*)(g_xbc + ((size_t)(bc * CHUNKL + tid)) * CONVDIM + DINNER + DSTATE + n0 + q * 4);
        const float* cf = (const float*)cv;
#pragma unroll
        for (int i = 0; i < 16; i++)
            Gs[i][tid] = tf32r(cf[i] * eal);
        {
            int p = tid >> 2, k4 = (tid & 3) << 2;
            float4 pvv = *(const float4*)(pv_base + (size_t)p * DSTATE + n0 + k4);
            Xs[k4 + 0][p] = tf32r(pvv.x); Xs[k4 + 1][p] = tf32r(pvv.y);
            Xs[k4 + 2][p] = tf32r(pvv.z); Xs[k4 + 3][p] = tf32r(pvv.w);
        }
        __syncthreads();
#pragma unroll
        for (int ks = 0; ks < 2; ks++) {
            int kb = ks * 8;
            unsigned af[2][4], bf[8][2];
#pragma unroll
            for (int mt = 0; mt < 2; mt++) {
                int m = wm + mt * 16;
                af[mt][0] = __float_as_uint(Gs[kb + tig][m + g]);
                af[mt][1] = __float_as_uint(Gs[kb + tig][m + g + 8]);
                af[mt][2] = __float_as_uint(Gs[kb + tig + 4][m + g]);
                af[mt][3] = __float_as_uint(Gs[kb + tig + 4][m + g + 8]);
            }
#pragma unroll
            for (int nt = 0; nt < 8; nt++) {
                int n = nt * 8;
                bf[nt][0] = __float_as_uint(Xs[kb + tig][n + g]);
                bf[nt][1] = __float_as_uint(Xs[kb + tig + 4][n + g]);
            }
#pragma unroll
            for (int mt = 0; mt < 2; mt++)
#pragma unroll
                for (int nt = 0; nt < 8; nt++)
                    mma_tf32(acc[mt][nt], af[mt], bf[nt]);
        }
        __syncthreads();
    }

    float Dh = Dp[h];
#pragma unroll
    for (int mt = 0; mt < 2; mt++) {
        int r0 = wm + mt * 16 + g;
#pragma unroll
        for (int nt = 0; nt < 8; nt++) {
            int pcol = nt * 8 + 2 * tig;
            int d = h * HEADDIM + pcol;
#pragma unroll
            for (int half = 0; half < 2; half++) {
                int l = r0 + half * 8;
                size_t row = (size_t)bc * CHUNKL + l;
                float xh0 = g_xbc[row * CONVDIM + d];
                float xh1 = g_xbc[row * CONVDIM + d + 1];
                float z0 = g_zx[row * DINPROJ + d];
                float z1 = g_zx[row * DINPROJ + d + 1];
                float v0 = acc[mt][nt][half * 2 + 0] + Dh * xh0;
                float v1 = acc[mt][nt][half * 2 + 1] + Dh * xh1;
                v0 *= siluf(z0);
                v1 *= siluf(z1);
                g_y[row * DINNER + d] = v0;
                g_y[row * DINNER + d + 1] = v1;
            }
        }
    }
}

// ---------------- gated RMS norm (float4 + shuffle reduction) ----------------
__global__ void rms_kernel(const float* __restrict__ rms_w)
{
    int row = blockIdx.x;
    int tid = threadIdx.x;
    float4* y4 = (float4*)(g_y + (size_t)row * DINNER);
    const float4* w4 = (const float4*)rms_w;
    __shared__ float red8[8];
    float4 v0 = y4[tid], v1 = y4[tid + 256];
    float ss = v0.x * v0.x + v0.y * v0.y + v0.z * v0.z + v0.w * v0.w
             + v1.x * v1.x + v1.y * v1.y + v1.z * v1.z + v1.w * v1.w;
    float tot = block_sum256(ss, red8, tid);
    __shared__ float sc;
    if (tid == 0) sc = rsqrtf(tot * (1.f / DINNER) + 1e-12f);
    __syncthreads();
    float scale = sc;
    float4 g0 = w4[tid], g1 = w4[tid + 256];
    v0.x *= scale * g0.x; v0.y *= scale * g0.y; v0.z *= scale * g0.z; v0.w *= scale * g0.w;
    v1.x *= scale * g1.x; v1.y *= scale * g1.y; v1.z *= scale * g1.z; v1.w *= scale * g1.w;
    y4[tid] = v0; y4[tid + 256] = v1;
}

// ---------------- residual add + LayerNorm (float4 + shuffle reduction) ------
__global__ void addln_kernel(const float* __restrict__ in1, const float* __restrict__ res,
                             const float* __restrict__ g, const float* __restrict__ bta,
                             float* __restrict__ out)
{
    int row = blockIdx.x;
    int tid = threadIdx.x;
    __shared__ float red8[8];
    __shared__ float s_mu, s_inv;
    float4 a = ((const float4*)(in1 + (size_t)row * DMODEL))[tid];
    float4 b = ((const float4*)(res + (size_t)row * DMODEL))[tid];
    float4 v;
    v.x = a.x + b.x; v.y = a.y + b.y; v.z = a.z + b.z; v.w = a.w + b.w;
    float s = (v.x + v.y) + (v.z + v.w);
    float tot = block_sum256(s, red8, tid);
    if (tid == 0) s_mu = tot * (1.f / DMODEL);
    __syncthreads();
    float mu = s_mu;
    float dx = v.x - mu, dy = v.y - mu, dz = v.z - mu, dw = v.w - mu;
    float vs = dx * dx + dy * dy + dz * dz + dw * dw;
    float vtot = block_sum256(vs, red8, tid);
    if (tid == 0) s_inv = rsqrtf(vtot * (1.f / DMODEL) + 1e-12f);
    __syncthreads();
    float inv = s_inv;
    float4 gg = ((const float4*)g)[tid];
    float4 bb = ((const float4*)bta)[tid];
    float4 o;
    o.x = dx * inv * gg.x + bb.x;
    o.y = dy * inv * gg.y + bb.y;
    o.z = dz * inv * gg.z + bb.z;
    o.w = dw * inv * gg.w + bb.w;
    ((float4*)(out + (size_t)row * DMODEL))[tid] = o;
}

// ---------------- launch ----------------
extern "C" void kernel_launch(void* const* d_in, const int* in_sizes, int n_in,
                              void* d_out, int out_size)
{
    const float* x          = (const float*)d_in[0];
    const float* time_diff  = (const float*)d_in[1];
    const float* W_in       = (const float*)d_in[2];
    const float* b_in       = (const float*)d_in[3];
    const float* conv_w     = (const float*)d_in[4];
    const float* conv_b     = (const float*)d_in[5];
    const float* A_log      = (const float*)d_in[6];
    const float* dt_bias    = (const float*)d_in[7];
    const float* Dp         = (const float*)d_in[8];
    const float* time_decay = (const float*)d_in[9];
    const float* rms_w      = (const float*)d_in[10];
    const float* W_out      = (const float*)d_in[11];
    const float* b_out      = (const float*)d_in[12];
    const float* ln_g       = (const float*)d_in[13];
    const float* ln_b       = (const float*)d_in[14];
    const float* fc1_w      = (const float*)d_in[15];
    const float* fc1_b      = (const float*)d_in[16];
    const float* fc2_w      = (const float*)d_in[17];
    const float* fc2_b      = (const float*)d_in[18];
    const float* ln2_g      = (const float*)d_in[19];
    const float* ln2_b      = (const float*)d_in[20];
    float* out = (float*)d_out;

    float *p_zx, *p_y, *p_hidden, *p_h, *p_ff, *p_ff2;
    cudaGetSymbolAddress((void**)&p_zx, g_zx);
    cudaGetSymbolAddress((void**)&p_y, g_y);
    cudaGetSymbolAddress((void**)&p_hidden, g_hidden);
    cudaGetSymbolAddress((void**)&p_h, g_h);
    cudaGetSymbolAddress((void**)&p_ff, g_ff);
    cudaGetSymbolAddress((void**)&p_ff2, g_ff2);

    cudaFuncSetAttribute(gemm_tc, cudaFuncAttributeMaxDynamicSharedMemorySize, GT_SMEM);

    // 1. in_proj
    gemm_tc<<<dim3((DINPROJ + 127) / 128, NROWS / 128), 256, GT_SMEM>>>(
        x, W_in, b_in, p_zx, NROWS, DINPROJ, DMODEL, 0);
    // 1b. exact fp32 dt_raw
    dtraw_kernel<<<NROWS / 8, 256>>>(x, W_in, b_in);
    // 2. dt / dA / chunk cumsum (shuffle scan)
    dtscan_kernel<<<BB * NHEADS * NC, CHUNKL>>>(time_diff, A_log, dt_bias, time_decay);
    // 3. conv + silu + fused xdt (4x4 vectorized)
    conv_kernel<<<((NROWS / 4) * (CONVDIM / 4) + 255) / 256, 256>>>(conv_w, conv_b);
    // 4. G = C @ B^T  [tf32, 64x64]
    cbgemm_kernel<<<dim3(4, 4, BB * NC), 256>>>();
    // 5. chunk states [tf32, __expf]
    states_kernel<<<BB * NC * NHEADS, 256>>>();
    // 6. inter-chunk scan [__expf]
    scan_kernel<<<(BB * NHEADS * HEADDIM * DSTATE + 255) / 256, 256>>>();
    // 7. Y [tf32, __expf]
    ydiag_kernel<<<BB * NC * NHEADS, 256>>>(Dp);
    // 8. gated RMS norm (vectorized)
    rms_kernel<<<NROWS, 256>>>(rms_w);
    // 9. out_proj
    gemm_tc<<<dim3(DMODEL / 128, NROWS / 128), 256, GT_SMEM>>>(
        p_y, W_out, b_out, p_hidden, NROWS, DMODEL, DINNER, 0);
    // 10. h = LN(hidden + x)  (vectorized)
    addln_kernel<<<NROWS, 256>>>(p_hidden, x, ln_g, ln_b, p_h);
    // 11. fc1 + hardswish
    gemm_tc<<<dim3(DFF / 128, NROWS / 128), 256, GT_SMEM>>>(
        p_h, fc1_w, fc1_b, p_ff, NROWS, DFF, DMODEL, 1);
    // 12. fc2
    gemm_tc<<<dim3(DMODEL / 128, NROWS / 128), 256, GT_SMEM>>>(
        p_ff, fc2_w, fc2_b, p_ff2, NROWS, DMODEL, DFF, 0);
    // 13. out = LN(ff2 + h)  (vectorized)
    addln_kernel<<<NROWS, 256>>>(p_ff2, p_h, ln2_g, ln2_b, out);
    // 14. time_diff passthrough
    cudaMemcpyAsync(out + (size_t)NROWS * DMODEL, time_diff,
                    (size_t)BB * SEQ * sizeof(float), cudaMemcpyDeviceToDevice);
}